// round 4
// baseline (speedup 1.0000x reference)
#include <cuda_runtime.h>
#include <cuda_fp16.h>
#include <math.h>
#include <stdint.h>

// ---------------- problem constants ----------------
#define NROWS   253952      // B*S*N = 16*512*31
#define DM      256
#define VOC     64
#define NN      31
#define TILE_M  128
#define GRID_M  (NROWS / TILE_M)   // 1984
#define NT      256

// ---------------- smem layout (bytes) ----------------
#define XPB     528           // activation row pitch (264 halfs, odd-16B -> conflict-free)
#define WPB     144           // weight row pitch (k-major, 72 halfs)
#define WBSZ    36864         // 256 * 144
#define PPB     272           // logits/probs row pitch (68 floats)

#define SM_X    0             // 128*528 = 67584
#define SM_Y    67584
#define SM_W0   135168        // team 0 weight buffer
#define SM_W1   172032        // team 1 weight buffer
#define SM_BF   208896        // bias feats (256 f32)
#define SM_E1   209920        // e1 = b_ln@W1 + b1
#define SM_E2   210944
#define SM_D1   211968        // d1 = g_ln@W1
#define SM_D2   212992
#define SM_ST   214016        // float2 st[2 parity][4 slot][128 row] = 8192
#define SMEM_BYTES 222208

// ---------------- prepped weights (device globals) ----------------
__device__ __align__(16) __half g_wf[65536];    // Wf fp16       [k][n]
__device__ __align__(16) __half g_w1g[65536];   // g_ln[k]*W1    [k][n]
__device__ __align__(16) __half g_w2g[65536];   // g_ln[k]*W2
__device__ __align__(16) __half g_wo[16384];    // W_out         [k][n(64)]
__device__ float g_d1[256], g_e1[256], g_d2[256], g_e2[256];

// ---------------- PTX helpers ----------------
__device__ __forceinline__ uint32_t smem_u32_of(const void* p) {
    uint32_t a;
    asm("{ .reg .u64 t; cvta.to.shared.u64 t, %1; cvt.u32.u64 %0, t; }" : "=r"(a) : "l"(p));
    return a;
}
__device__ __forceinline__ void ldsm_x4(uint32_t* r, uint32_t addr) {
    asm volatile("ldmatrix.sync.aligned.m8n8.x4.shared.b16 {%0,%1,%2,%3}, [%4];"
        : "=r"(r[0]), "=r"(r[1]), "=r"(r[2]), "=r"(r[3]) : "r"(addr));
}
__device__ __forceinline__ void ldsm_x4_t(uint32_t* r, uint32_t addr) {
    asm volatile("ldmatrix.sync.aligned.m8n8.x4.trans.shared.b16 {%0,%1,%2,%3}, [%4];"
        : "=r"(r[0]), "=r"(r[1]), "=r"(r[2]), "=r"(r[3]) : "r"(addr));
}
__device__ __forceinline__ void mma16816(float* d, const uint32_t* a, const uint32_t* b) {
    asm volatile("mma.sync.aligned.m16n8k16.row.col.f32.f16.f16.f32 "
        "{%0,%1,%2,%3}, {%4,%5,%6,%7}, {%8,%9}, {%0,%1,%2,%3};"
        : "+f"(d[0]), "+f"(d[1]), "+f"(d[2]), "+f"(d[3])
        : "r"(a[0]), "r"(a[1]), "r"(a[2]), "r"(a[3]), "r"(b[0]), "r"(b[1]));
}
#define CP_ASYNC16(dst, src) \
    asm volatile("cp.async.cg.shared.global [%0], [%1], 16;" :: "r"(dst), "l"(src) : "memory")
#define CP_COMMIT() asm volatile("cp.async.commit_group;" ::: "memory")
#define CP_WAIT0()  asm volatile("cp.async.wait_group 0;" ::: "memory")
#define BAR_TEAM(id) asm volatile("bar.sync %0, 128;" :: "r"(id) : "memory")

// ---------------- math helpers ----------------
__device__ __forceinline__ float gelu_exact(float x) {
    return 0.5f * x * (1.0f + erff(x * 0.70710678118654752f));
}
__device__ __forceinline__ uint32_t pk(float a, float b) {
    __half2 h = __floats2half2_rn(a, b);
    return *reinterpret_cast<uint32_t*>(&h);
}

// ---------------- prep kernels ----------------
__global__ void prep_weights(const float* __restrict__ Wf, const float* __restrict__ W1,
                             const float* __restrict__ W2, const float* __restrict__ Wo,
                             const float* __restrict__ lg) {
    int idx = blockIdx.x * blockDim.x + threadIdx.x;   // 832*256 = 212992
    if (idx < 65536) {
        g_wf[idx] = __float2half_rn(Wf[idx]);
    } else if (idx < 131072) {
        int e = idx - 65536;
        g_w1g[e] = __float2half_rn(lg[e >> 8] * W1[e]);
    } else if (idx < 196608) {
        int e = idx - 131072;
        g_w2g[e] = __float2half_rn(lg[e >> 8] * W2[e]);
    } else {
        int e = idx - 196608;
        g_wo[e] = __float2half_rn(Wo[e]);
    }
}
__global__ void prep_vecs(const float* __restrict__ W1, const float* __restrict__ b1,
                          const float* __restrict__ W2, const float* __restrict__ b2,
                          const float* __restrict__ lg, const float* __restrict__ lb) {
    int n = threadIdx.x;  // 256
    float d1 = 0.f, e1 = 0.f, d2 = 0.f, e2 = 0.f;
    for (int k = 0; k < 256; k++) {
        float g = lg[k], b = lb[k];
        float w1 = W1[k * 256 + n], w2 = W2[k * 256 + n];
        d1 += g * w1; e1 += b * w1;
        d2 += g * w2; e2 += b * w2;
    }
    g_d1[n] = d1; g_e1[n] = e1 + b1[n];
    g_d2[n] = d2; g_e2[n] = e2 + b2[n];
}

// ---------------- weight chunk issue (cp.async, per team: 128 threads) ----------------
template<int C16, int GP>   // C16: 16B chunks per k-row (8 for 64 cols, 4 for 32); GP: global pitch halfs
__device__ __forceinline__ void issue_w(uint32_t dstb, int t128, const __half* src) {
    #pragma unroll
    for (int i = t128; i < 256 * C16; i += 128) {
        int k = i / C16, c = i % C16;
        CP_ASYNC16(dstb + k * WPB + (c << 4),
                   (const uint8_t*)(src + (size_t)k * GP) + (c << 4));
    }
    CP_COMMIT();
}

template<int S> __device__ __forceinline__ const __half* stage_wptr() {
    return (S == 0) ? g_wf : (S == 1) ? g_w1g : g_w2g;
}

// ---------------- one stage: 2 chunks (cols team*64 and team*64+128) ----------------
template<int S>
__device__ __forceinline__ void stage_body(
    uint8_t* sm, uint32_t smb, int tid, int lane, int team, int m_grp, int n_grp,
    int gr0, const float* __restrict__ memory, uint32_t in_ofs, uint32_t out_ofs, uint32_t w_ofs)
{
    const int barid = 1 + team;
    const int t128 = tid & 127;
    float st1[4], st2[4], st1b[4], st2b[4];
    #pragma unroll
    for (int u = 0; u < 4; u++) { st1[u] = 0.f; st2[u] = 0.f; st1b[u] = 0.f; st2b[u] = 0.f; }

    const float* sBF = (const float*)(sm + SM_BF);
    const float* sD  = (const float*)(sm + (S == 1 ? SM_D1 : SM_D2));
    const float* sE  = (const float*)(sm + (S == 1 ? SM_E1 : SM_E2));
    const float2* stRd = (const float2*)(sm + SM_ST) + (((S > 0 ? S - 1 : 0) & 1) * 512);
    float2* stWr = (float2*)(sm + SM_ST) + ((S & 1) * 512);

    #pragma unroll
    for (int ph = 0; ph < 2; ph++) {
        const int j = team + ph * 2;
        CP_WAIT0();
        BAR_TEAM(barid);

        // ---- GEMM: warp tile 64M x 32N, K=256 ----
        float acc[4][4][4] = {};
        const uint32_t a_addr = smb + in_ofs + (uint32_t)(m_grp * 64 + (lane & 15)) * XPB + ((lane >> 4) << 4);
        const uint32_t b_addr = smb + w_ofs + (uint32_t)(lane & 15) * WPB + ((lane >> 4) << 4) + n_grp * 64;
        #pragma unroll
        for (int k0 = 0; k0 < 256; k0 += 16) {
            uint32_t A[4][4];
            #pragma unroll
            for (int u = 0; u < 4; u++) ldsm_x4(A[u], a_addr + (uint32_t)u * (16 * XPB) + k0 * 2);
            uint32_t B[2][4];
            #pragma unroll
            for (int t = 0; t < 2; t++) ldsm_x4_t(B[t], b_addr + (uint32_t)k0 * WPB + t * 32);
            #pragma unroll
            for (int u = 0; u < 4; u++) {
                #pragma unroll
                for (int t = 0; t < 2; t++) {
                    mma16816(acc[u][2 * t],     A[u], B[t]);
                    mma16816(acc[u][2 * t + 1], A[u], B[t] + 2);
                }
            }
        }
        BAR_TEAM(barid);   // all team warps done reading W buffer

        // ---- prefetch next weight chunk into the freed buffer ----
        if (ph == 0)       issue_w<8, 256>(smb + w_ofs, t128, stage_wptr<S>() + (team + 2) * 64);
        else if (S < 2)    issue_w<8, 256>(smb + w_ofs, t128, stage_wptr<(S < 2 ? S + 1 : 2)>() + team * 64);
        else               issue_w<4, 64>(smb + w_ofs, t128, g_wo + team * 32);

        // ---- epilogue ----
        const int cb = j * 64 + n_grp * 32 + 2 * (lane & 3);
        #pragma unroll
        for (int u = 0; u < 4; u++) {
            const int rA = m_grp * 64 + u * 16 + (lane >> 2);
            const int rB = rA + 8;
            const float* mA = nullptr; const float* mB = nullptr;
            float rsA = 0.f, muRsA = 0.f, rsB = 0.f, muRsB = 0.f;
            if (S == 0) {
                mA = memory + (size_t)((gr0 + rA) / NN) * DM;
                mB = memory + (size_t)((gr0 + rB) / NN) * DM;
            } else {
                float2 p0 = stRd[rA], p1 = stRd[128 + rA], p2 = stRd[256 + rA], p3 = stRd[384 + rA];
                float s1 = (p0.x + p1.x) + (p2.x + p3.x), s2 = (p0.y + p1.y) + (p2.y + p3.y);
                float mu = s1 * (1.0f / 256.0f);
                rsA = rsqrtf(s2 * (1.0f / 256.0f) - mu * mu + 1e-5f);
                muRsA = mu * rsA;
                float2 q0 = stRd[rB], q1 = stRd[128 + rB], q2 = stRd[256 + rB], q3 = stRd[384 + rB];
                float t1 = (q0.x + q1.x) + (q2.x + q3.x), t2 = (q0.y + q1.y) + (q2.y + q3.y);
                float muB = t1 * (1.0f / 256.0f);
                rsB = rsqrtf(t2 * (1.0f / 256.0f) - muB * muB + 1e-5f);
                muRsB = muB * rsB;
            }
            #pragma unroll
            for (int v = 0; v < 4; v++) {
                const int c = cb + 8 * v;
                float x0 = acc[u][v][0], x1 = acc[u][v][1];
                float x2 = acc[u][v][2], x3 = acc[u][v][3];
                if (S == 0) {
                    float b0 = sBF[c], b1v = sBF[c + 1];
                    x0 = gelu_exact(x0 + b0);  x1 = gelu_exact(x1 + b1v);
                    x2 = gelu_exact(x2 + b0);  x3 = gelu_exact(x3 + b1v);
                    float2 m0 = *(const float2*)(mA + c);
                    float2 m1 = *(const float2*)(mB + c);
                    x0 += m0.x; x1 += m0.y; x2 += m1.x; x3 += m1.y;
                } else {
                    float2 dv = *(const float2*)(sD + c);
                    float2 ev = *(const float2*)(sE + c);
                    x0 = gelu_exact(fmaf(rsA, x0, fmaf(-muRsA, dv.x, ev.x)));
                    x1 = gelu_exact(fmaf(rsA, x1, fmaf(-muRsA, dv.y, ev.y)));
                    x2 = gelu_exact(fmaf(rsB, x2, fmaf(-muRsB, dv.x, ev.x)));
                    x3 = gelu_exact(fmaf(rsB, x3, fmaf(-muRsB, dv.y, ev.y)));
                }
                if (S < 2) {
                    st1[u]  += x0 + x1;           st2[u]  += x0 * x0 + x1 * x1;
                    st1b[u] += x2 + x3;           st2b[u] += x2 * x2 + x3 * x3;
                }
                *(uint32_t*)(sm + out_ofs + (uint32_t)rA * XPB + c * 2) = pk(x0, x1);
                *(uint32_t*)(sm + out_ofs + (uint32_t)rB * XPB + c * 2) = pk(x2, x3);
            }
        }
    }

    if (S < 2) {
        #pragma unroll
        for (int u = 0; u < 4; u++) {
            #pragma unroll
            for (int off = 1; off <= 2; off <<= 1) {
                st1[u]  += __shfl_xor_sync(0xffffffffu, st1[u],  off);
                st2[u]  += __shfl_xor_sync(0xffffffffu, st2[u],  off);
                st1b[u] += __shfl_xor_sync(0xffffffffu, st1b[u], off);
                st2b[u] += __shfl_xor_sync(0xffffffffu, st2b[u], off);
            }
        }
        if ((lane & 3) == 0) {
            const int slot = (team * 2 + n_grp) * 128;
            #pragma unroll
            for (int u = 0; u < 4; u++) {
                const int rA = m_grp * 64 + u * 16 + (lane >> 2);
                stWr[slot + rA]     = make_float2(st1[u],  st2[u]);
                stWr[slot + rA + 8] = make_float2(st1b[u], st2b[u]);
            }
        }
    }
}

// ---------------- main fused kernel ----------------
__global__ void __launch_bounds__(NT, 1)
dec_main(const float* __restrict__ memory, const int* __restrict__ fidx,
         const float* __restrict__ emb, const float* __restrict__ bf,
         float* __restrict__ out)
{
    extern __shared__ __align__(16) uint8_t sm[];
    const int tid   = threadIdx.x;
    const int wid   = tid >> 5;
    const int lane  = tid & 31;
    const int team  = wid >> 2;
    const int w4    = wid & 3;
    const int m_grp = w4 >> 1;
    const int n_grp = w4 & 1;
    const int gr0   = blockIdx.x * TILE_M;
    const uint32_t smb = smem_u32_of(sm);
    const uint32_t w_ofs = team ? SM_W1 : SM_W0;
    const int barid = 1 + team;

    // first weight chunk for this team (stage 0, col block team*64)
    issue_w<8, 256>(smb + w_ofs, tid & 127, g_wf + team * 64);

    // params
    {
        int i = tid;
        ((float*)(sm + SM_BF))[i] = bf[i];
        ((float*)(sm + SM_E1))[i] = g_e1[i];
        ((float*)(sm + SM_E2))[i] = g_e2[i];
        ((float*)(sm + SM_D1))[i] = g_d1[i];
        ((float*)(sm + SM_D2))[i] = g_d2[i];
    }

    // gather: X = fp16(emb[feat_idx])
    for (int q = tid; q < TILE_M * 8; q += NT) {
        int row = q >> 3, c32 = (q & 7) << 5;
        int e = __ldg(fidx + gr0 + row);
        const float4* src = (const float4*)(emb + (size_t)e * DM + c32);
        uint4* dst = (uint4*)(sm + SM_X + (uint32_t)row * XPB + c32 * 2);
        #pragma unroll
        for (int u = 0; u < 4; u++) {
            float4 f0 = __ldg(src + 2 * u);
            float4 f1 = __ldg(src + 2 * u + 1);
            uint4 p;
            p.x = pk(f0.x, f0.y); p.y = pk(f0.z, f0.w);
            p.z = pk(f1.x, f1.y); p.w = pk(f1.z, f1.w);
            dst[u] = p;
        }
    }
    __syncthreads();

    stage_body<0>(sm, smb, tid, lane, team, m_grp, n_grp, gr0, memory, SM_X, SM_Y, w_ofs);
    __syncthreads();
    stage_body<1>(sm, smb, tid, lane, team, m_grp, n_grp, gr0, memory, SM_Y, SM_X, w_ofs);
    __syncthreads();
    stage_body<2>(sm, smb, tid, lane, team, m_grp, n_grp, gr0, memory, SM_X, SM_Y, w_ofs);
    __syncthreads();

    // ---- logits: in = SM_Y, Wo half per team (32 cols), warp tile 32M x 32N ----
    CP_WAIT0();
    BAR_TEAM(barid);
    {
        float acc[2][4][4] = {};
        const uint32_t a_addr = smb + SM_Y + (uint32_t)(w4 * 32 + (lane & 15)) * XPB + ((lane >> 4) << 4);
        const uint32_t b_addr = smb + w_ofs + (uint32_t)(lane & 15) * WPB + ((lane >> 4) << 4);
        #pragma unroll
        for (int k0 = 0; k0 < 256; k0 += 16) {
            uint32_t A[2][4];
            #pragma unroll
            for (int u = 0; u < 2; u++) ldsm_x4(A[u], a_addr + (uint32_t)u * (16 * XPB) + k0 * 2);
            uint32_t B[2][4];
            #pragma unroll
            for (int t = 0; t < 2; t++) ldsm_x4_t(B[t], b_addr + (uint32_t)k0 * WPB + t * 32);
            #pragma unroll
            for (int u = 0; u < 2; u++) {
                #pragma unroll
                for (int t = 0; t < 2; t++) {
                    mma16816(acc[u][2 * t],     A[u], B[t]);
                    mma16816(acc[u][2 * t + 1], A[u], B[t] + 2);
                }
            }
        }
        // write logits fp32 into SM_X area (pitch PPB)
        #pragma unroll
        for (int u = 0; u < 2; u++) {
            const int rA = w4 * 32 + u * 16 + (lane >> 2);
            const int rB = rA + 8;
            #pragma unroll
            for (int v = 0; v < 4; v++) {
                const int c = team * 32 + 8 * v + 2 * (lane & 3);
                *(float2*)(sm + SM_X + (uint32_t)rA * PPB + c * 4) = make_float2(acc[u][v][0], acc[u][v][1]);
                *(float2*)(sm + SM_X + (uint32_t)rB * PPB + c * 4) = make_float2(acc[u][v][2], acc[u][v][3]);
            }
        }
    }
    __syncthreads();

    // ---- softmax: one thread per row ----
    if (tid < TILE_M) {
        const uint8_t* rowp = sm + SM_X + (uint32_t)tid * PPB;
        float4 v[16];
        float mx = -1e30f;
        #pragma unroll
        for (int i = 0; i < 16; i++) {
            v[i] = *(const float4*)(rowp + i * 16);
            mx = fmaxf(mx, fmaxf(fmaxf(v[i].x, v[i].y), fmaxf(v[i].z, v[i].w)));
        }
        float s = 0.f;
        #pragma unroll
        for (int i = 0; i < 16; i++) {
            v[i].x = expf(v[i].x - mx); v[i].y = expf(v[i].y - mx);
            v[i].z = expf(v[i].z - mx); v[i].w = expf(v[i].w - mx);
            s += (v[i].x + v[i].y) + (v[i].z + v[i].w);
        }
        const float inv = 1.0f / s;
        float4* orow = (float4*)(out + (size_t)(gr0 + tid) * VOC);
        #pragma unroll
        for (int i = 0; i < 16; i++) {
            v[i].x *= inv; v[i].y *= inv; v[i].z *= inv; v[i].w *= inv;
            orow[i] = v[i];
        }
    }
}

// ---------------- harness entry ----------------
extern "C" void kernel_launch(void* const* d_in, const int* in_sizes, int n_in,
                              void* d_out, int out_size)
{
    const float* memory   = (const float*)d_in[0];
    const int*   feat_idx = (const int*)  d_in[1];
    const float* emb      = (const float*)d_in[2];
    const float* Wf       = (const float*)d_in[3];
    const float* bf       = (const float*)d_in[4];
    const float* lg       = (const float*)d_in[5];
    const float* lb       = (const float*)d_in[6];
    const float* W1       = (const float*)d_in[7];
    const float* b1       = (const float*)d_in[8];
    const float* W2       = (const float*)d_in[9];
    const float* b2       = (const float*)d_in[10];
    const float* Wo       = (const float*)d_in[11];
    float* out = (float*)d_out;

    cudaFuncSetAttribute(dec_main, cudaFuncAttributeMaxDynamicSharedMemorySize, SMEM_BYTES);

    prep_weights<<<832, 256>>>(Wf, W1, W2, Wo, lg);
    prep_vecs<<<1, 256>>>(W1, b1, W2, b2, lg, lb);
    dec_main<<<GRID_M, NT, SMEM_BYTES>>>(memory, feat_idx, emb, bf, out);
}

// round 5
// speedup vs baseline: 1.3380x; 1.3380x over previous
#include <cuda_runtime.h>
#include <cuda_fp16.h>
#include <math.h>
#include <stdint.h>

// ---------------- problem constants ----------------
#define NROWS   253952      // B*S*N = 16*512*31
#define DM      256
#define VOC     64
#define NN      31
#define TILE_M  128
#define GRID_M  (NROWS / TILE_M)   // 1984
#define NT      512

// ---------------- smem layout (bytes) ----------------
#define XPB     528           // activation row pitch (264 halfs; odd-16B -> conflict-free ldsm)
#define WPB     144           // weight row pitch (72 halfs)
#define PPB     272           // logits row pitch (68 floats)

#define SM_X    0             // 128*528 = 67584
#define SM_Y    67584
#define SM_W0   135168        // weight chunk buffer 0 (36864)
#define SM_W1   172032        // weight chunk buffer 1
#define SM_BF   208896        // bias feats (256 f32)
#define SM_E1   209920        // e1 = lb@W1 + b1
#define SM_E2   210944
#define SM_D1   211968        // d1 = lg@W1
#define SM_D2   212992
#define SM_ST   214016        // float2 st[2 parity][2 ngrp][128] = 4096
#define SMEM_BYTES 218112

// ---------------- prepped weights ----------------
__device__ __align__(16) __half g_wf[65536];    // Wf fp16        [k][n]
__device__ __align__(16) __half g_w1g[65536];   // lg[k]*W1       [k][n]
__device__ __align__(16) __half g_w2g[65536];   // lg[k]*W2       [k][n]
__device__ __align__(16) __half g_wo[16384];    // W_out          [k][n(64)]
__device__ float g_d1[256], g_e1[256], g_d2[256], g_e2[256];

// ---------------- PTX helpers ----------------
__device__ __forceinline__ uint32_t smem_u32_of(const void* p) {
    uint32_t a;
    asm("{ .reg .u64 t; cvta.to.shared.u64 t, %1; cvt.u32.u64 %0, t; }" : "=r"(a) : "l"(p));
    return a;
}
__device__ __forceinline__ void ldsm_x4(uint32_t* r, uint32_t addr) {
    asm volatile("ldmatrix.sync.aligned.m8n8.x4.shared.b16 {%0,%1,%2,%3}, [%4];"
        : "=r"(r[0]), "=r"(r[1]), "=r"(r[2]), "=r"(r[3]) : "r"(addr));
}
__device__ __forceinline__ void ldsm_x4_t(uint32_t* r, uint32_t addr) {
    asm volatile("ldmatrix.sync.aligned.m8n8.x4.trans.shared.b16 {%0,%1,%2,%3}, [%4];"
        : "=r"(r[0]), "=r"(r[1]), "=r"(r[2]), "=r"(r[3]) : "r"(addr));
}
__device__ __forceinline__ void mma16816(float* d, const uint32_t* a, const uint32_t* b) {
    asm volatile("mma.sync.aligned.m16n8k16.row.col.f32.f16.f16.f32 "
        "{%0,%1,%2,%3}, {%4,%5,%6,%7}, {%8,%9}, {%0,%1,%2,%3};"
        : "+f"(d[0]), "+f"(d[1]), "+f"(d[2]), "+f"(d[3])
        : "r"(a[0]), "r"(a[1]), "r"(a[2]), "r"(a[3]), "r"(b[0]), "r"(b[1]));
}
#define CP_ASYNC16(dst, src) \
    asm volatile("cp.async.cg.shared.global [%0], [%1], 16;" :: "r"(dst), "l"(src) : "memory")
#define CP_COMMIT() asm volatile("cp.async.commit_group;" ::: "memory")
#define CP_WAIT0()  asm volatile("cp.async.wait_group 0;" ::: "memory")

// ---------------- math helpers ----------------
__device__ __forceinline__ float gelu_exact(float x) {
    return 0.5f * x * (1.0f + erff(x * 0.70710678118654752f));
}
__device__ __forceinline__ uint32_t pk(float a, float b) {
    __half2 h = __floats2half2_rn(a, b);
    return *reinterpret_cast<uint32_t*>(&h);
}

// ---------------- prep kernels (verified in R4) ----------------
__global__ void prep_weights(const float* __restrict__ Wf, const float* __restrict__ W1,
                             const float* __restrict__ W2, const float* __restrict__ Wo,
                             const float* __restrict__ lg) {
    int idx = blockIdx.x * blockDim.x + threadIdx.x;   // 832*256 = 212992
    if (idx < 65536) {
        g_wf[idx] = __float2half_rn(Wf[idx]);
    } else if (idx < 131072) {
        int e = idx - 65536;
        g_w1g[e] = __float2half_rn(lg[e >> 8] * W1[e]);
    } else if (idx < 196608) {
        int e = idx - 131072;
        g_w2g[e] = __float2half_rn(lg[e >> 8] * W2[e]);
    } else {
        int e = idx - 196608;
        g_wo[e] = __float2half_rn(Wo[e]);
    }
}
__global__ void prep_vecs(const float* __restrict__ W1, const float* __restrict__ b1,
                          const float* __restrict__ W2, const float* __restrict__ b2,
                          const float* __restrict__ lg, const float* __restrict__ lb) {
    int n = threadIdx.x;  // 256
    float d1 = 0.f, e1 = 0.f, d2 = 0.f, e2 = 0.f;
    for (int k = 0; k < 256; k++) {
        float g = lg[k], b = lb[k];
        float w1 = W1[k * 256 + n], w2 = W2[k * 256 + n];
        d1 += g * w1; e1 += b * w1;
        d2 += g * w2; e2 += b * w2;
    }
    g_d1[n] = d1; g_e1[n] = e1 + b1[n];
    g_d2[n] = d2; g_e2[n] = e2 + b2[n];
}

// ---------------- weight chunk issue (all 512 threads) ----------------
template<int GP>   // global pitch in halfs
__device__ __forceinline__ void issue_w(uint32_t dstb, int tid, const __half* src) {
    #pragma unroll
    for (int i = tid; i < 2048; i += NT) {   // 256 k-rows x 8 x 16B
        int k = i >> 3, c = i & 7;
        CP_ASYNC16(dstb + k * WPB + (c << 4),
                   (const uint8_t*)(src + (size_t)k * GP) + (c << 4));
    }
    CP_COMMIT();
}
// chunk c: 0..3 -> Wf cols c*64; 4..7 -> W1g; 8..11 -> W2g; 12 -> Wo (full 64)
__device__ __forceinline__ void issue_chunk(uint32_t smb, int tid, int c) {
    uint32_t dst = smb + ((c & 1) ? SM_W1 : SM_W0);
    if (c < 12) {
        const __half* W = (c < 4) ? g_wf : (c < 8) ? g_w1g : g_w2g;
        issue_w<256>(dst, tid, W + (c & 3) * 64);
    } else {
        issue_w<64>(dst, tid, g_wo);
    }
}

// ---------------- one stage: 4 chunks of 64 cols ----------------
template<int S>
__device__ __forceinline__ void stage_run(
    uint8_t* sm, uint32_t smb, int tid, int lane, int m_grp, int n_grp,
    int gr0, const float* __restrict__ memory, uint32_t in_ofs, uint32_t out_ofs)
{
    const int r0  = m_grp * 16;
    const int rlo = r0 + (lane >> 2);
    const int rhi = rlo + 8;
    const float* sBF = (const float*)(sm + SM_BF);
    const float* sD  = (const float*)(sm + (S == 1 ? SM_D1 : SM_D2));
    const float* sE  = (const float*)(sm + (S == 1 ? SM_E1 : SM_E2));
    const float2* stRd = (const float2*)(sm + SM_ST) + ((S == 1 ? 0 : 1) * 256);
    float2* stWr       = (float2*)(sm + SM_ST) + ((S & 1) * 256);
    const float* mlo = memory + (size_t)((gr0 + rlo) / NN) * DM;
    const float* mhi = memory + (size_t)((gr0 + rhi) / NN) * DM;

    float st1lo = 0.f, st2lo = 0.f, st1hi = 0.f, st2hi = 0.f;

    for (int jc = 0; jc < 4; jc++) {
        const int c = S * 4 + jc;
        CP_WAIT0();
        __syncthreads();          // chunk c landed; all warps past GEMM(c-1)
        issue_chunk(smb, tid, c + 1);

        // ---- GEMM: warp tile 16M x 32N, K=256 ----
        const uint32_t wbase  = smb + ((c & 1) ? SM_W1 : SM_W0);
        const uint32_t a_addr = smb + in_ofs + (uint32_t)(r0 + (lane & 15)) * XPB + ((lane >> 4) << 4);
        const uint32_t b_addr = wbase + (uint32_t)(lane & 15) * WPB + ((lane >> 4) << 4) + n_grp * 64;
        float acc[4][4] = {};
        #pragma unroll
        for (int k0 = 0; k0 < 256; k0 += 16) {
            uint32_t A[4];
            ldsm_x4(A, a_addr + k0 * 2);
            uint32_t B0[4], B1[4];
            ldsm_x4_t(B0, b_addr + (uint32_t)k0 * WPB);
            ldsm_x4_t(B1, b_addr + (uint32_t)k0 * WPB + 32);
            mma16816(acc[0], A, B0); mma16816(acc[1], A, B0 + 2);
            mma16816(acc[2], A, B1); mma16816(acc[3], A, B1 + 2);
        }

        // ---- epilogue ----
        float rsA = 0.f, mrA = 0.f, rsB = 0.f, mrB = 0.f;
        if (S > 0) {
            float2 p0 = stRd[rlo], p1 = stRd[128 + rlo];
            float mu = (p0.x + p1.x) * (1.0f / 256.0f);
            rsA = rsqrtf((p0.y + p1.y) * (1.0f / 256.0f) - mu * mu + 1e-5f);
            mrA = mu * rsA;
            float2 q0 = stRd[rhi], q1 = stRd[128 + rhi];
            float muB = (q0.x + q1.x) * (1.0f / 256.0f);
            rsB = rsqrtf((q0.y + q1.y) * (1.0f / 256.0f) - muB * muB + 1e-5f);
            mrB = muB * rsB;
        }
        const int cb = jc * 64 + n_grp * 32 + 2 * (lane & 3);
        #pragma unroll
        for (int v = 0; v < 4; v++) {
            const int cc = cb + 8 * v;
            float x0 = acc[v][0], x1 = acc[v][1], x2 = acc[v][2], x3 = acc[v][3];
            if (S == 0) {
                float b0 = sBF[cc], b1v = sBF[cc + 1];
                x0 = gelu_exact(x0 + b0);  x1 = gelu_exact(x1 + b1v);
                x2 = gelu_exact(x2 + b0);  x3 = gelu_exact(x3 + b1v);
                float2 m0 = *(const float2*)(mlo + cc);
                float2 m1 = *(const float2*)(mhi + cc);
                x0 += m0.x; x1 += m0.y; x2 += m1.x; x3 += m1.y;
            } else {
                float2 dv = *(const float2*)(sD + cc);
                float2 ev = *(const float2*)(sE + cc);
                x0 = gelu_exact(fmaf(rsA, x0, fmaf(-mrA, dv.x, ev.x)));
                x1 = gelu_exact(fmaf(rsA, x1, fmaf(-mrA, dv.y, ev.y)));
                x2 = gelu_exact(fmaf(rsB, x2, fmaf(-mrB, dv.x, ev.x)));
                x3 = gelu_exact(fmaf(rsB, x3, fmaf(-mrB, dv.y, ev.y)));
            }
            if (S < 2) {
                st1lo += x0 + x1;  st2lo += x0 * x0 + x1 * x1;
                st1hi += x2 + x3;  st2hi += x2 * x2 + x3 * x3;
            }
            *(uint32_t*)(sm + out_ofs + (uint32_t)rlo * XPB + cc * 2) = pk(x0, x1);
            *(uint32_t*)(sm + out_ofs + (uint32_t)rhi * XPB + cc * 2) = pk(x2, x3);
        }
    }

    if (S < 2) {
        #pragma unroll
        for (int off = 1; off <= 2; off <<= 1) {
            st1lo += __shfl_xor_sync(0xffffffffu, st1lo, off);
            st2lo += __shfl_xor_sync(0xffffffffu, st2lo, off);
            st1hi += __shfl_xor_sync(0xffffffffu, st1hi, off);
            st2hi += __shfl_xor_sync(0xffffffffu, st2hi, off);
        }
        if ((lane & 3) == 0) {
            stWr[n_grp * 128 + rlo] = make_float2(st1lo, st2lo);
            stWr[n_grp * 128 + rhi] = make_float2(st1hi, st2hi);
        }
    }
}

// ---------------- main fused kernel ----------------
__global__ void __launch_bounds__(NT, 1)
dec_main(const float* __restrict__ memory, const int* __restrict__ fidx,
         const float* __restrict__ emb, const float* __restrict__ bf,
         float* __restrict__ out)
{
    extern __shared__ __align__(16) uint8_t sm[];
    const int tid   = threadIdx.x;
    const int wid   = tid >> 5;
    const int lane  = tid & 31;
    const int m_grp = wid >> 1;      // 0..7
    const int n_grp = wid & 1;       // 0..1
    const int gr0   = blockIdx.x * TILE_M;
    const uint32_t smb = smem_u32_of(sm);

    issue_chunk(smb, tid, 0);        // first weight chunk in flight ASAP

    if (tid < 256) {
        int i = tid;
        ((float*)(sm + SM_BF))[i] = bf[i];
        ((float*)(sm + SM_E1))[i] = g_e1[i];
        ((float*)(sm + SM_E2))[i] = g_e2[i];
        ((float*)(sm + SM_D1))[i] = g_d1[i];
        ((float*)(sm + SM_D2))[i] = g_d2[i];
    }

    // gather: X = fp16(emb[feat_idx])
    for (int q = tid; q < TILE_M * 8; q += NT) {
        int row = q >> 3, c32 = (q & 7) << 5;
        int e = __ldg(fidx + gr0 + row);
        const float4* src = (const float4*)(emb + (size_t)e * DM + c32);
        uint4* dst = (uint4*)(sm + SM_X + (uint32_t)row * XPB + c32 * 2);
        #pragma unroll
        for (int u = 0; u < 4; u++) {
            float4 f0 = __ldg(src + 2 * u);
            float4 f1 = __ldg(src + 2 * u + 1);
            uint4 p;
            p.x = pk(f0.x, f0.y); p.y = pk(f0.z, f0.w);
            p.z = pk(f1.x, f1.y); p.w = pk(f1.z, f1.w);
            dst[u] = p;
        }
    }
    // (first chunk's CP_WAIT0+sync inside stage_run covers gather + params)

    stage_run<0>(sm, smb, tid, lane, m_grp, n_grp, gr0, memory, SM_X, SM_Y);
    stage_run<1>(sm, smb, tid, lane, m_grp, n_grp, gr0, memory, SM_Y, SM_X);
    stage_run<2>(sm, smb, tid, lane, m_grp, n_grp, gr0, memory, SM_X, SM_Y);

    // ---- logits chunk (c=12, buffer 0): in = SM_Y, write fp32 logits into SM_X ----
    CP_WAIT0();
    __syncthreads();
    {
        const int r0  = m_grp * 16;
        const int rlo = r0 + (lane >> 2);
        const int rhi = rlo + 8;
        const uint32_t a_addr = smb + SM_Y + (uint32_t)(r0 + (lane & 15)) * XPB + ((lane >> 4) << 4);
        const uint32_t b_addr = smb + SM_W0 + (uint32_t)(lane & 15) * WPB + ((lane >> 4) << 4) + n_grp * 64;
        float acc[4][4] = {};
        #pragma unroll
        for (int k0 = 0; k0 < 256; k0 += 16) {
            uint32_t A[4];
            ldsm_x4(A, a_addr + k0 * 2);
            uint32_t B0[4], B1[4];
            ldsm_x4_t(B0, b_addr + (uint32_t)k0 * WPB);
            ldsm_x4_t(B1, b_addr + (uint32_t)k0 * WPB + 32);
            mma16816(acc[0], A, B0); mma16816(acc[1], A, B0 + 2);
            mma16816(acc[2], A, B1); mma16816(acc[3], A, B1 + 2);
        }
        #pragma unroll
        for (int v = 0; v < 4; v++) {
            const int cc = n_grp * 32 + 8 * v + 2 * (lane & 3);
            *(float2*)(sm + SM_X + (uint32_t)rlo * PPB + cc * 4) = make_float2(acc[v][0], acc[v][1]);
            *(float2*)(sm + SM_X + (uint32_t)rhi * PPB + cc * 4) = make_float2(acc[v][2], acc[v][3]);
        }
    }
    __syncthreads();

    // ---- softmax: one thread per row, in place ----
    if (tid < TILE_M) {
        uint8_t* rowp = sm + SM_X + (uint32_t)tid * PPB;
        float4 v[16];
        float mx = -1e30f;
        #pragma unroll
        for (int i = 0; i < 16; i++) {
            v[i] = *(const float4*)(rowp + i * 16);
            mx = fmaxf(mx, fmaxf(fmaxf(v[i].x, v[i].y), fmaxf(v[i].z, v[i].w)));
        }
        float s = 0.f;
        #pragma unroll
        for (int i = 0; i < 16; i++) {
            v[i].x = expf(v[i].x - mx); v[i].y = expf(v[i].y - mx);
            v[i].z = expf(v[i].z - mx); v[i].w = expf(v[i].w - mx);
            s += (v[i].x + v[i].y) + (v[i].z + v[i].w);
        }
        const float inv = 1.0f / s;
        #pragma unroll
        for (int i = 0; i < 16; i++) {
            v[i].x *= inv; v[i].y *= inv; v[i].z *= inv; v[i].w *= inv;
            *(float4*)(rowp + i * 16) = v[i];
        }
    }
    __syncthreads();

    // ---- coalesced output store ----
    float* og = out + (size_t)gr0 * VOC;
    #pragma unroll
    for (int i = tid; i < TILE_M * VOC / 4; i += NT) {   // 2048 float4
        int row = i >> 4, c4 = i & 15;
        *(float4*)(og + row * VOC + c4 * 4) =
            *(const float4*)(sm + SM_X + (uint32_t)row * PPB + c4 * 16);
    }
}

// ---------------- harness entry ----------------
extern "C" void kernel_launch(void* const* d_in, const int* in_sizes, int n_in,
                              void* d_out, int out_size)
{
    const float* memory   = (const float*)d_in[0];
    const int*   feat_idx = (const int*)  d_in[1];
    const float* emb      = (const float*)d_in[2];
    const float* Wf       = (const float*)d_in[3];
    const float* bf       = (const float*)d_in[4];
    const float* lg       = (const float*)d_in[5];
    const float* lb       = (const float*)d_in[6];
    const float* W1       = (const float*)d_in[7];
    const float* b1       = (const float*)d_in[8];
    const float* W2       = (const float*)d_in[9];
    const float* b2       = (const float*)d_in[10];
    const float* Wo       = (const float*)d_in[11];
    float* out = (float*)d_out;

    cudaFuncSetAttribute(dec_main, cudaFuncAttributeMaxDynamicSharedMemorySize, SMEM_BYTES);

    prep_weights<<<832, 256>>>(Wf, W1, W2, Wo, lg);
    prep_vecs<<<1, 256>>>(W1, b1, W2, b2, lg, lb);
    dec_main<<<GRID_M, NT, SMEM_BYTES>>>(memory, feat_idx, emb, bf, out);
}

// round 6
// speedup vs baseline: 1.6205x; 1.2112x over previous
#include <cuda_runtime.h>
#include <cuda_fp16.h>
#include <math.h>
#include <stdint.h>

// ---------------- problem constants ----------------
#define NROWS   253952      // B*S*N = 16*512*31
#define DM      256
#define VOC     64
#define NN      31
#define TILE_M  128
#define GRID_M  (NROWS / TILE_M)   // 1984
#define NT      512

// ---------------- smem layout (bytes) ----------------
#define XPB     528           // activation row pitch (264 halfs; 528%128=16 -> conflict-free ldsm)
#define WPB     144           // weight row pitch (72 halfs)
#define WBSZ    36864         // one 64-col weight slot: 256 * 144
#define PPB     272           // logits row pitch (68 floats)

#define SM_X    0             // 128*528 = 67584 (single activation buffer, overwritten in place)
#define SM_W    67584         // 4 ring slots x 36864 = 147456 -> 215040
#define SM_LG   (SM_W + WBSZ) // logits area reuses ring slot 1 during softmax
#define SM_BF   215040
#define SM_D1   216064
#define SM_E1   217088
#define SM_D2   218112
#define SM_E2   219136
#define SM_ST   220160        // float2 [2 parity][4 n_grp][128 rows] = 8192
#define SMEM_BYTES 228352

// ---------------- prepped device globals ----------------
__device__ __align__(16) __half g_wf[65536];    // Wf fp16      [k][n]
__device__ __align__(16) __half g_w1g[65536];   // lg[k]*W1     [k][n]
__device__ __align__(16) __half g_w2g[65536];   // lg[k]*W2     [k][n]
__device__ __align__(16) __half g_wo[16384];    // W_out        [k][n(64)]
__device__ __align__(16) __half g_embh[4096 * 256];  // fp16 embedding table
__device__ float g_d1[256], g_e1[256], g_d2[256], g_e2[256];

// ---------------- PTX helpers ----------------
__device__ __forceinline__ uint32_t smem_u32_of(const void* p) {
    uint32_t a;
    asm("{ .reg .u64 t; cvta.to.shared.u64 t, %1; cvt.u32.u64 %0, t; }" : "=r"(a) : "l"(p));
    return a;
}
__device__ __forceinline__ void ldsm_x4(uint32_t* r, uint32_t addr) {
    asm volatile("ldmatrix.sync.aligned.m8n8.x4.shared.b16 {%0,%1,%2,%3}, [%4];"
        : "=r"(r[0]), "=r"(r[1]), "=r"(r[2]), "=r"(r[3]) : "r"(addr));
}
__device__ __forceinline__ void ldsm_x4_t(uint32_t* r, uint32_t addr) {
    asm volatile("ldmatrix.sync.aligned.m8n8.x4.trans.shared.b16 {%0,%1,%2,%3}, [%4];"
        : "=r"(r[0]), "=r"(r[1]), "=r"(r[2]), "=r"(r[3]) : "r"(addr));
}
__device__ __forceinline__ void mma16816(float* d, const uint32_t* a, const uint32_t* b) {
    asm volatile("mma.sync.aligned.m16n8k16.row.col.f32.f16.f16.f32 "
        "{%0,%1,%2,%3}, {%4,%5,%6,%7}, {%8,%9}, {%0,%1,%2,%3};"
        : "+f"(d[0]), "+f"(d[1]), "+f"(d[2]), "+f"(d[3])
        : "r"(a[0]), "r"(a[1]), "r"(a[2]), "r"(a[3]), "r"(b[0]), "r"(b[1]));
}
#define CP_ASYNC16(dst, src) \
    asm volatile("cp.async.cg.shared.global [%0], [%1], 16;" :: "r"(dst), "l"(src) : "memory")
#define CP_COMMIT() asm volatile("cp.async.commit_group;" ::: "memory")
#define CP_WAIT1()  asm volatile("cp.async.wait_group 1;" ::: "memory")
#define CP_WAIT0()  asm volatile("cp.async.wait_group 0;" ::: "memory")

// ---------------- math helpers ----------------
__device__ __forceinline__ float gelu_exact(float x) {
    return 0.5f * x * (1.0f + erff(x * 0.70710678118654752f));
}
__device__ __forceinline__ uint32_t pk(float a, float b) {
    __half2 h = __floats2half2_rn(a, b);
    return *reinterpret_cast<uint32_t*>(&h);
}

// ---------------- prep kernels ----------------
__global__ void prep_weights(const float* __restrict__ Wf, const float* __restrict__ W1,
                             const float* __restrict__ W2, const float* __restrict__ Wo,
                             const float* __restrict__ lg) {
    int idx = blockIdx.x * blockDim.x + threadIdx.x;   // 832*256 = 212992
    if (idx < 65536) {
        g_wf[idx] = __float2half_rn(Wf[idx]);
    } else if (idx < 131072) {
        int e = idx - 65536;
        g_w1g[e] = __float2half_rn(lg[e >> 8] * W1[e]);
    } else if (idx < 196608) {
        int e = idx - 131072;
        g_w2g[e] = __float2half_rn(lg[e >> 8] * W2[e]);
    } else {
        int e = idx - 196608;
        g_wo[e] = __float2half_rn(Wo[e]);
    }
}
__global__ void prep_emb(const float* __restrict__ emb) {
    int idx = blockIdx.x * blockDim.x + threadIdx.x;   // 4096*256 = 1048576
    g_embh[idx] = __float2half_rn(emb[idx]);
}
__global__ void prep_vecs(const float* __restrict__ W1, const float* __restrict__ b1,
                          const float* __restrict__ W2, const float* __restrict__ b2,
                          const float* __restrict__ lg, const float* __restrict__ lb) {
    int n = threadIdx.x;  // 256
    float d1 = 0.f, e1 = 0.f, d2 = 0.f, e2 = 0.f;
    for (int k = 0; k < 256; k++) {
        float g = lg[k], b = lb[k];
        float w1 = W1[k * 256 + n], w2 = W2[k * 256 + n];
        d1 += g * w1; e1 += b * w1;
        d2 += g * w2; e2 += b * w2;
    }
    g_d1[n] = d1; g_e1[n] = e1 + b1[n];
    g_d2[n] = d2; g_e2[n] = e2 + b2[n];
}

// ---------------- weight pair issue ----------------
__device__ __forceinline__ void issue_64(uint32_t dst, int tid, const __half* src, int gp) {
    #pragma unroll
    for (int i = tid; i < 2048; i += NT) {   // 256 k-rows x 8 x 16B
        int k = i >> 3, c = i & 7;
        CP_ASYNC16(dst + k * WPB + (c << 4),
                   (const uint8_t*)(src + (size_t)k * gp) + (c << 4));
    }
}
// pair p (0..6): p<6 -> stage p/2 cols (p&1)*128..+127 into slots {2(p&1), 2(p&1)+1}
//                p==6 -> Wo into slot 0
__device__ __forceinline__ void issue_pair(uint32_t smb, int tid, int p) {
    uint32_t base = smb + SM_W + (uint32_t)((p & 1) * 2) * WBSZ;
    if (p < 6) {
        const __half* W = (p < 2) ? g_wf : (p < 4) ? g_w1g : g_w2g;
        const __half* src = W + (p & 1) * 128;
        issue_64(base, tid, src, 256);
        issue_64(base + WBSZ, tid, src + 64, 256);
    } else {
        issue_64(base, tid, g_wo, 64);
    }
    CP_COMMIT();
}

// ---------------- one stage: 2 macro-chunks of 128 cols, outputs in regs ----------------
template<int S>
__device__ __forceinline__ void stage_run(
    uint8_t* sm, uint32_t smb, int tid, int lane, int m_grp, int n_grp,
    int gr0, const float* __restrict__ memory)
{
    const int rq = lane >> 2;
    const float* sBF = (const float*)(sm + SM_BF);
    const float* sD  = (const float*)(sm + (S == 1 ? SM_D1 : SM_D2));
    const float* sE  = (const float*)(sm + (S == 1 ? SM_E1 : SM_E2));

    uint32_t outr[2][2][2][4];     // [macro][mi][h][v] packed half2
    float s1[4] = {0.f, 0.f, 0.f, 0.f}, s2[4] = {0.f, 0.f, 0.f, 0.f};
    float rs[4], mrs[4];
    const float* mr[4];

    #pragma unroll
    for (int g = 0; g < 2; g++) {
        const int pair = 2 * S + g;
        CP_WAIT1();
        __syncthreads();           // pair landed; everyone past prior phase

        // ---- GEMM: warp tile 32M x 32N, K=256 ----
        const int slot = (pair & 1) * 2 + (n_grp >> 1);
        const uint32_t a_addr = smb + SM_X + (uint32_t)(m_grp * 32 + (lane & 15)) * XPB + ((lane >> 4) << 4);
        const uint32_t b_addr = smb + SM_W + (uint32_t)slot * WBSZ
                              + (uint32_t)(lane & 15) * WPB + ((lane >> 4) << 4) + (n_grp & 1) * 64;
        float acc[2][4][4] = {};
        #pragma unroll
        for (int k0 = 0; k0 < 256; k0 += 16) {
            uint32_t A0[4], A1[4], B0[4], B1[4];
            ldsm_x4(A0, a_addr + k0 * 2);
            ldsm_x4(A1, a_addr + 16 * XPB + k0 * 2);
            ldsm_x4_t(B0, b_addr + (uint32_t)k0 * WPB);
            ldsm_x4_t(B1, b_addr + (uint32_t)k0 * WPB + 32);
            mma16816(acc[0][0], A0, B0); mma16816(acc[0][1], A0, B0 + 2);
            mma16816(acc[0][2], A0, B1); mma16816(acc[0][3], A0, B1 + 2);
            mma16816(acc[1][0], A1, B0); mma16816(acc[1][1], A1, B0 + 2);
            mma16816(acc[1][2], A1, B1); mma16816(acc[1][3], A1, B1 + 2);
        }
        __syncthreads();           // all warps done reading this pair's slots
        if (pair + 2 <= 6) issue_pair(smb, tid, pair + 2);

        // ---- per-row coefficients (once) ----
        if (g == 0) {
            if (S == 0) {
                #pragma unroll
                for (int q = 0; q < 4; q++) {
                    int r = m_grp * 32 + (q >> 1) * 16 + (q & 1) * 8 + rq;
                    mr[q] = memory + (size_t)((gr0 + r) / NN) * DM;
                }
            } else {
                const float2* stRd = (const float2*)(sm + SM_ST) + (uint32_t)((S - 1) & 1) * 512;
                #pragma unroll
                for (int q = 0; q < 4; q++) {
                    int r = m_grp * 32 + (q >> 1) * 16 + (q & 1) * 8 + rq;
                    float2 p0 = stRd[r], p1 = stRd[128 + r], p2 = stRd[256 + r], p3 = stRd[384 + r];
                    float a1 = (p0.x + p1.x) + (p2.x + p3.x);
                    float a2 = (p0.y + p1.y) + (p2.y + p3.y);
                    float mu = a1 * (1.0f / 256.0f);
                    rs[q]  = rsqrtf(a2 * (1.0f / 256.0f) - mu * mu + 1e-5f);
                    mrs[q] = mu * rs[q];
                }
            }
        }

        // ---- epilogue into registers ----
        const int cbase = g * 128 + n_grp * 32 + 2 * (lane & 3);
        #pragma unroll
        for (int mi = 0; mi < 2; mi++) {
            #pragma unroll
            for (int v = 0; v < 4; v++) {
                const int c = cbase + v * 8;
                float x0 = acc[mi][v][0], x1 = acc[mi][v][1];
                float x2 = acc[mi][v][2], x3 = acc[mi][v][3];
                if (S == 0) {
                    float b0 = sBF[c], b1v = sBF[c + 1];
                    x0 = gelu_exact(x0 + b0);  x1 = gelu_exact(x1 + b1v);
                    x2 = gelu_exact(x2 + b0);  x3 = gelu_exact(x3 + b1v);
                    float2 m0 = *(const float2*)(mr[mi * 2] + c);
                    float2 m1 = *(const float2*)(mr[mi * 2 + 1] + c);
                    x0 += m0.x; x1 += m0.y; x2 += m1.x; x3 += m1.y;
                } else {
                    float2 dv = *(const float2*)(sD + c);
                    float2 ev = *(const float2*)(sE + c);
                    x0 = gelu_exact(fmaf(rs[mi * 2], x0, fmaf(-mrs[mi * 2], dv.x, ev.x)));
                    x1 = gelu_exact(fmaf(rs[mi * 2], x1, fmaf(-mrs[mi * 2], dv.y, ev.y)));
                    x2 = gelu_exact(fmaf(rs[mi * 2 + 1], x2, fmaf(-mrs[mi * 2 + 1], dv.x, ev.x)));
                    x3 = gelu_exact(fmaf(rs[mi * 2 + 1], x3, fmaf(-mrs[mi * 2 + 1], dv.y, ev.y)));
                }
                if (S < 2) {
                    s1[mi * 2]     += x0 + x1;  s2[mi * 2]     += x0 * x0 + x1 * x1;
                    s1[mi * 2 + 1] += x2 + x3;  s2[mi * 2 + 1] += x2 * x2 + x3 * x3;
                }
                outr[g][mi][0][v] = pk(x0, x1);
                outr[g][mi][1][v] = pk(x2, x3);
            }
        }
    }

    // ---- stats write (S<2) ----
    if (S < 2) {
        #pragma unroll
        for (int q = 0; q < 4; q++) {
            #pragma unroll
            for (int off = 1; off <= 2; off <<= 1) {
                s1[q] += __shfl_xor_sync(0xffffffffu, s1[q], off);
                s2[q] += __shfl_xor_sync(0xffffffffu, s2[q], off);
            }
        }
        if ((lane & 3) == 0) {
            float2* stWr = (float2*)(sm + SM_ST) + (uint32_t)(S & 1) * 512 + n_grp * 128;
            #pragma unroll
            for (int q = 0; q < 4; q++) {
                int r = m_grp * 32 + (q >> 1) * 16 + (q & 1) * 8 + rq;
                stWr[r] = make_float2(s1[q], s2[q]);
            }
        }
    }

    // ---- X writeback in place (safe: everyone past macro-B GEMM sync) ----
    #pragma unroll
    for (int g = 0; g < 2; g++) {
        const int cbase = g * 128 + n_grp * 32 + 2 * (lane & 3);
        #pragma unroll
        for (int mi = 0; mi < 2; mi++) {
            const int rA = m_grp * 32 + mi * 16 + rq;
            #pragma unroll
            for (int v = 0; v < 4; v++) {
                const int c = cbase + v * 8;
                *(uint32_t*)(sm + SM_X + (uint32_t)rA * XPB + c * 2)       = outr[g][mi][0][v];
                *(uint32_t*)(sm + SM_X + (uint32_t)(rA + 8) * XPB + c * 2) = outr[g][mi][1][v];
            }
        }
    }
    // next stage's wait+sync orders these writes before reads
}

// ---------------- main fused kernel ----------------
__global__ void __launch_bounds__(NT, 1)
dec_main(const float* __restrict__ memory, const int* __restrict__ fidx,
         const float* __restrict__ bf, float* __restrict__ out)
{
    extern __shared__ __align__(16) uint8_t sm[];
    const int tid   = threadIdx.x;
    const int wid   = tid >> 5;
    const int lane  = tid & 31;
    const int m_grp = wid & 3;       // 0..3 (32-row block)
    const int n_grp = wid >> 2;      // 0..3 (32-col block within 128-col macro)
    const int gr0   = blockIdx.x * TILE_M;
    const uint32_t smb = smem_u32_of(sm);

    // gather via cp.async from fp16 emb table (group 0)
    #pragma unroll
    for (int i = tid; i < TILE_M * 32; i += NT) {
        int row = i >> 5, c = i & 31;
        int e = __ldg(fidx + gr0 + row);
        CP_ASYNC16(smb + SM_X + (uint32_t)row * XPB + (c << 4),
                   (const uint8_t*)(g_embh + (size_t)e * DM) + (c << 4));
    }
    CP_COMMIT();

    issue_pair(smb, tid, 0);   // groups 1,2
    issue_pair(smb, tid, 1);

    if (tid < 256) {
        int i = tid;
        ((float*)(sm + SM_BF))[i] = bf[i];
        ((float*)(sm + SM_D1))[i] = g_d1[i];
        ((float*)(sm + SM_E1))[i] = g_e1[i];
        ((float*)(sm + SM_D2))[i] = g_d2[i];
        ((float*)(sm + SM_E2))[i] = g_e2[i];
    }

    stage_run<0>(sm, smb, tid, lane, m_grp, n_grp, gr0, memory);
    stage_run<1>(sm, smb, tid, lane, m_grp, n_grp, gr0, memory);
    stage_run<2>(sm, smb, tid, lane, m_grp, n_grp, gr0, memory);

    // ---- logits: warp tile 16M x 32N (8 m-groups x 2 n-groups), Wo in slot 0 ----
    CP_WAIT0();
    __syncthreads();
    {
        const int m2 = wid >> 1, n2 = wid & 1;
        const int rq = lane >> 2;
        const uint32_t a_addr = smb + SM_X + (uint32_t)(m2 * 16 + (lane & 15)) * XPB + ((lane >> 4) << 4);
        const uint32_t b_addr = smb + SM_W + (uint32_t)(lane & 15) * WPB + ((lane >> 4) << 4) + n2 * 64;
        float acc[4][4] = {};
        #pragma unroll
        for (int k0 = 0; k0 < 256; k0 += 16) {
            uint32_t A[4], B0[4], B1[4];
            ldsm_x4(A, a_addr + k0 * 2);
            ldsm_x4_t(B0, b_addr + (uint32_t)k0 * WPB);
            ldsm_x4_t(B1, b_addr + (uint32_t)k0 * WPB + 32);
            mma16816(acc[0], A, B0); mma16816(acc[1], A, B0 + 2);
            mma16816(acc[2], A, B1); mma16816(acc[3], A, B1 + 2);
        }
        const int rlo = m2 * 16 + rq, rhi = rlo + 8;
        #pragma unroll
        for (int v = 0; v < 4; v++) {
            const int c = n2 * 32 + v * 8 + 2 * (lane & 3);
            *(float2*)(sm + SM_LG + (uint32_t)rlo * PPB + c * 4) = make_float2(acc[v][0], acc[v][1]);
            *(float2*)(sm + SM_LG + (uint32_t)rhi * PPB + c * 4) = make_float2(acc[v][2], acc[v][3]);
        }
    }
    __syncthreads();

    // ---- softmax: one thread per row ----
    if (tid < TILE_M) {
        uint8_t* rowp = sm + SM_LG + (uint32_t)tid * PPB;
        float4 v[16];
        float mx = -1e30f;
        #pragma unroll
        for (int i = 0; i < 16; i++) {
            v[i] = *(const float4*)(rowp + i * 16);
            mx = fmaxf(mx, fmaxf(fmaxf(v[i].x, v[i].y), fmaxf(v[i].z, v[i].w)));
        }
        float s = 0.f;
        #pragma unroll
        for (int i = 0; i < 16; i++) {
            v[i].x = __expf(v[i].x - mx); v[i].y = __expf(v[i].y - mx);
            v[i].z = __expf(v[i].z - mx); v[i].w = __expf(v[i].w - mx);
            s += (v[i].x + v[i].y) + (v[i].z + v[i].w);
        }
        const float inv = 1.0f / s;
        #pragma unroll
        for (int i = 0; i < 16; i++) {
            v[i].x *= inv; v[i].y *= inv; v[i].z *= inv; v[i].w *= inv;
            *(float4*)(rowp + i * 16) = v[i];
        }
    }
    __syncthreads();

    // ---- coalesced output store ----
    float* og = out + (size_t)gr0 * VOC;
    #pragma unroll
    for (int i = tid; i < TILE_M * VOC / 4; i += NT) {   // 2048 float4
        int row = i >> 4, c4 = i & 15;
        *(float4*)(og + row * VOC + c4 * 4) =
            *(const float4*)(sm + SM_LG + (uint32_t)row * PPB + c4 * 16);
    }
}

// ---------------- harness entry ----------------
extern "C" void kernel_launch(void* const* d_in, const int* in_sizes, int n_in,
                              void* d_out, int out_size)
{
    const float* memory   = (const float*)d_in[0];
    const int*   feat_idx = (const int*)  d_in[1];
    const float* emb      = (const float*)d_in[2];
    const float* Wf       = (const float*)d_in[3];
    const float* bf       = (const float*)d_in[4];
    const float* lg       = (const float*)d_in[5];
    const float* lb       = (const float*)d_in[6];
    const float* W1       = (const float*)d_in[7];
    const float* b1       = (const float*)d_in[8];
    const float* W2       = (const float*)d_in[9];
    const float* b2       = (const float*)d_in[10];
    const float* Wo       = (const float*)d_in[11];
    float* out = (float*)d_out;

    cudaFuncSetAttribute(dec_main, cudaFuncAttributeMaxDynamicSharedMemorySize, SMEM_BYTES);

    prep_weights<<<832, 256>>>(Wf, W1, W2, Wo, lg);
    prep_emb<<<4096, 256>>>(emb);
    prep_vecs<<<1, 256>>>(W1, b1, W2, b2, lg, lb);
    dec_main<<<GRID_M, NT, SMEM_BYTES>>>(memory, feat_idx, bf, out);
}

// round 7
// speedup vs baseline: 1.7108x; 1.0557x over previous
#include <cuda_runtime.h>
#include <cuda_fp16.h>
#include <math.h>
#include <stdint.h>

// ---------------- problem constants ----------------
#define NROWS   253952      // B*S*N = 16*512*31
#define DM      256
#define VOC     64
#define NN      31
#define TILE_M  64
#define GRID_M  (NROWS / TILE_M)   // 3968
#define NT      256

// ---------------- smem layout (bytes) ----------------
#define XPB     528           // activation row pitch (33*16 -> conflict-free ldsm)
#define WPB     272           // weight slot row pitch (17*16; 128 cols + pad)
#define SLOTSZ  34816         // 128 k-rows * 272
#define PPB     272           // logits row pitch

#define SM_X    0             // 64*528 = 33792
#define SM_W    33792         // 2 slots -> 103424
#define SM_LG   SM_W          // logits reuse slot area after last GEMM
#define SM_ST   103424        // float2 [2 parity][4 ngrp][64 rows] = 4096
#define SMEM_BYTES 107520     // 105 KB -> 2 CTAs/SM

// ---------------- prepped device globals ----------------
__device__ __align__(16) __half g_wf[65536];    // Wf fp16      [k][n]
__device__ __align__(16) __half g_w1g[65536];   // lg[k]*W1     [k][n]
__device__ __align__(16) __half g_w2g[65536];   // lg[k]*W2     [k][n]
__device__ __align__(16) __half g_wo[16384];    // W_out        [k][64]
__device__ __align__(16) __half g_embh[4096 * 256];  // fp16 embedding table
__device__ float g_d1[256], g_e1[256], g_d2[256], g_e2[256];

// ---------------- PTX helpers ----------------
__device__ __forceinline__ uint32_t smem_u32_of(const void* p) {
    uint32_t a;
    asm("{ .reg .u64 t; cvta.to.shared.u64 t, %1; cvt.u32.u64 %0, t; }" : "=r"(a) : "l"(p));
    return a;
}
__device__ __forceinline__ void ldsm_x4(uint32_t* r, uint32_t addr) {
    asm volatile("ldmatrix.sync.aligned.m8n8.x4.shared.b16 {%0,%1,%2,%3}, [%4];"
        : "=r"(r[0]), "=r"(r[1]), "=r"(r[2]), "=r"(r[3]) : "r"(addr));
}
__device__ __forceinline__ void ldsm_x4_t(uint32_t* r, uint32_t addr) {
    asm volatile("ldmatrix.sync.aligned.m8n8.x4.trans.shared.b16 {%0,%1,%2,%3}, [%4];"
        : "=r"(r[0]), "=r"(r[1]), "=r"(r[2]), "=r"(r[3]) : "r"(addr));
}
__device__ __forceinline__ void mma16816(float* d, const uint32_t* a, const uint32_t* b) {
    asm volatile("mma.sync.aligned.m16n8k16.row.col.f32.f16.f16.f32 "
        "{%0,%1,%2,%3}, {%4,%5,%6,%7}, {%8,%9}, {%0,%1,%2,%3};"
        : "+f"(d[0]), "+f"(d[1]), "+f"(d[2]), "+f"(d[3])
        : "r"(a[0]), "r"(a[1]), "r"(a[2]), "r"(a[3]), "r"(b[0]), "r"(b[1]));
}
#define CP_ASYNC16(dst, src) \
    asm volatile("cp.async.cg.shared.global [%0], [%1], 16;" :: "r"(dst), "l"(src) : "memory")
#define CP_COMMIT() asm volatile("cp.async.commit_group;" ::: "memory")
#define CP_WAIT0()  asm volatile("cp.async.wait_group 0;" ::: "memory")

// ---------------- math helpers ----------------
__device__ __forceinline__ float gelu_exact(float x) {
    return 0.5f * x * (1.0f + erff(x * 0.70710678118654752f));
}
__device__ __forceinline__ uint32_t pk(float a, float b) {
    __half2 h = __floats2half2_rn(a, b);
    return *reinterpret_cast<uint32_t*>(&h);
}

// ---------------- prep kernels (verified R4-R6) ----------------
__global__ void prep_weights(const float* __restrict__ Wf, const float* __restrict__ W1,
                             const float* __restrict__ W2, const float* __restrict__ Wo,
                             const float* __restrict__ lg) {
    int idx = blockIdx.x * blockDim.x + threadIdx.x;   // 832*256
    if (idx < 65536) {
        g_wf[idx] = __float2half_rn(Wf[idx]);
    } else if (idx < 131072) {
        int e = idx - 65536;
        g_w1g[e] = __float2half_rn(lg[e >> 8] * W1[e]);
    } else if (idx < 196608) {
        int e = idx - 131072;
        g_w2g[e] = __float2half_rn(lg[e >> 8] * W2[e]);
    } else {
        int e = idx - 196608;
        g_wo[e] = __float2half_rn(Wo[e]);
    }
}
__global__ void prep_emb(const float* __restrict__ emb) {
    int idx = blockIdx.x * blockDim.x + threadIdx.x;   // 4096*256
    g_embh[idx] = __float2half_rn(emb[idx]);
}
__global__ void prep_vecs(const float* __restrict__ W1, const float* __restrict__ b1,
                          const float* __restrict__ W2, const float* __restrict__ b2,
                          const float* __restrict__ lg, const float* __restrict__ lb) {
    int n = threadIdx.x;  // 256
    float d1 = 0.f, e1 = 0.f, d2 = 0.f, e2 = 0.f;
    for (int k = 0; k < 256; k++) {
        float g = lg[k], b = lb[k];
        float w1 = W1[k * 256 + n], w2 = W2[k * 256 + n];
        d1 += g * w1; e1 += b * w1;
        d2 += g * w2; e2 += b * w2;
    }
    g_d1[n] = d1; g_e1[n] = e1 + b1[n];
    g_d2[n] = d2; g_e2[n] = e2 + b2[n];
}

// ---------------- half-chunk issue ----------------
// h 0..11: chunk c=h>>1 (128 cols), K-half kh=h&1. c: 0,1->Wf 2,3->W1g 4,5->W2g.
// h 12..13: Wo K-halves (64 cols).
__device__ __forceinline__ void issue_half(uint32_t smb, int tid, int h) {
    if (h > 13) return;
    uint32_t dst = smb + SM_W + (uint32_t)(h & 1) * SLOTSZ;
    if (h < 12) {
        const int c = h >> 1, kh = h & 1;
        const __half* W = (c < 2) ? g_wf : (c < 4) ? g_w1g : g_w2g;
        const __half* src = W + (size_t)(kh * 128) * 256 + (c & 1) * 128;
        #pragma unroll
        for (int i = tid; i < 2048; i += NT) {          // 128 k-rows x 16 x 16B
            int k = i >> 4, ch = i & 15;
            CP_ASYNC16(dst + k * WPB + (ch << 4),
                       (const uint8_t*)(src + (size_t)k * 256) + (ch << 4));
        }
    } else {
        const __half* src = g_wo + (size_t)((h & 1) * 128) * 64;
        #pragma unroll
        for (int i = tid; i < 1024; i += NT) {          // 128 k-rows x 8 x 16B
            int k = i >> 3, ch = i & 7;
            CP_ASYNC16(dst + k * WPB + (ch << 4),
                       (const uint8_t*)(src + (size_t)k * 64) + (ch << 4));
        }
    }
    CP_COMMIT();
}

// ---------------- one stage: 2 chunks x 128 cols, K in 2 ring halves ----------------
template<int S>
__device__ __forceinline__ void stage_run(
    uint8_t* sm, uint32_t smb, int tid, int lane, int m_grp, int n_grp,
    int gr0, const float* __restrict__ memory, const float* __restrict__ bf)
{
    const int rq = lane >> 2;
    const float* sD = (S == 1) ? g_d1 : g_d2;
    const float* sE = (S == 1) ? g_e1 : g_e2;

    // per-row coefficients (stats from stage S-1 are sync-ordered already)
    float rs[4], mrs[4];
    const float* mr[4];
    #pragma unroll
    for (int q = 0; q < 4; q++) {
        int r = m_grp * 32 + (q >> 1) * 16 + (q & 1) * 8 + rq;
        if (S == 0) {
            mr[q] = memory + (size_t)((gr0 + r) / NN) * DM;
        } else {
            const float2* stRd = (const float2*)(sm + SM_ST) + (uint32_t)((S - 1) & 1) * 256;
            float2 p0 = stRd[r], p1 = stRd[64 + r], p2 = stRd[128 + r], p3 = stRd[192 + r];
            float a1 = (p0.x + p1.x) + (p2.x + p3.x);
            float a2 = (p0.y + p1.y) + (p2.y + p3.y);
            float mu = a1 * (1.0f / 256.0f);
            rs[q]  = rsqrtf(a2 * (1.0f / 256.0f) - mu * mu + 1e-5f);
            mrs[q] = mu * rs[q];
        }
    }

    uint32_t outr[2][2][2][4];
    float s1[4] = {0.f, 0.f, 0.f, 0.f}, s2[4] = {0.f, 0.f, 0.f, 0.f};

    #pragma unroll
    for (int g = 0; g < 2; g++) {
        const int c = 2 * S + g;
        float acc[2][4][4] = {};
        #pragma unroll
        for (int kh = 0; kh < 2; kh++) {
            const int h = 2 * c + kh;
            CP_WAIT0();
            __syncthreads();               // load h landed; slot (h+1)&1 free
            issue_half(smb, tid, h + 1);

            const uint32_t a_addr = smb + SM_X + (uint32_t)(m_grp * 32 + (lane & 15)) * XPB
                                  + ((lane >> 4) << 4) + kh * 256;
            const uint32_t b_addr = smb + SM_W + (uint32_t)(h & 1) * SLOTSZ
                                  + (uint32_t)(lane & 15) * WPB + ((lane >> 4) << 4) + n_grp * 64;
            #pragma unroll
            for (int k0 = 0; k0 < 128; k0 += 16) {
                uint32_t A0[4], A1[4], B0[4], B1[4];
                ldsm_x4(A0, a_addr + k0 * 2);
                ldsm_x4(A1, a_addr + 16 * XPB + k0 * 2);
                ldsm_x4_t(B0, b_addr + (uint32_t)k0 * WPB);
                ldsm_x4_t(B1, b_addr + (uint32_t)k0 * WPB + 32);
                mma16816(acc[0][0], A0, B0); mma16816(acc[0][1], A0, B0 + 2);
                mma16816(acc[0][2], A0, B1); mma16816(acc[0][3], A0, B1 + 2);
                mma16816(acc[1][0], A1, B0); mma16816(acc[1][1], A1, B0 + 2);
                mma16816(acc[1][2], A1, B1); mma16816(acc[1][3], A1, B1 + 2);
            }
        }

        // ---- epilogue into registers ----
        const int cbase = g * 128 + n_grp * 32 + 2 * (lane & 3);
        #pragma unroll
        for (int mi = 0; mi < 2; mi++) {
            #pragma unroll
            for (int v = 0; v < 4; v++) {
                const int cc = cbase + v * 8;
                float x0 = acc[mi][v][0], x1 = acc[mi][v][1];
                float x2 = acc[mi][v][2], x3 = acc[mi][v][3];
                if (S == 0) {
                    float2 bv = __ldg((const float2*)(bf + cc));
                    x0 = gelu_exact(x0 + bv.x);  x1 = gelu_exact(x1 + bv.y);
                    x2 = gelu_exact(x2 + bv.x);  x3 = gelu_exact(x3 + bv.y);
                    float2 m0 = *(const float2*)(mr[mi * 2] + cc);
                    float2 m1 = *(const float2*)(mr[mi * 2 + 1] + cc);
                    x0 += m0.x; x1 += m0.y; x2 += m1.x; x3 += m1.y;
                } else {
                    float2 dv = __ldg((const float2*)(sD + cc));
                    float2 ev = __ldg((const float2*)(sE + cc));
                    x0 = gelu_exact(fmaf(rs[mi * 2], x0, fmaf(-mrs[mi * 2], dv.x, ev.x)));
                    x1 = gelu_exact(fmaf(rs[mi * 2], x1, fmaf(-mrs[mi * 2], dv.y, ev.y)));
                    x2 = gelu_exact(fmaf(rs[mi * 2 + 1], x2, fmaf(-mrs[mi * 2 + 1], dv.x, ev.x)));
                    x3 = gelu_exact(fmaf(rs[mi * 2 + 1], x3, fmaf(-mrs[mi * 2 + 1], dv.y, ev.y)));
                }
                if (S < 2) {
                    s1[mi * 2]     += x0 + x1;  s2[mi * 2]     += x0 * x0 + x1 * x1;
                    s1[mi * 2 + 1] += x2 + x3;  s2[mi * 2 + 1] += x2 * x2 + x3 * x3;
                }
                outr[g][mi][0][v] = pk(x0, x1);
                outr[g][mi][1][v] = pk(x2, x3);
            }
        }
    }

    // ---- stats ----
    if (S < 2) {
        #pragma unroll
        for (int q = 0; q < 4; q++) {
            #pragma unroll
            for (int off = 1; off <= 2; off <<= 1) {
                s1[q] += __shfl_xor_sync(0xffffffffu, s1[q], off);
                s2[q] += __shfl_xor_sync(0xffffffffu, s2[q], off);
            }
        }
        if ((lane & 3) == 0) {
            float2* stWr = (float2*)(sm + SM_ST) + (uint32_t)(S & 1) * 256 + n_grp * 64;
            #pragma unroll
            for (int q = 0; q < 4; q++) {
                int r = m_grp * 32 + (q >> 1) * 16 + (q & 1) * 8 + rq;
                stWr[r] = make_float2(s1[q], s2[q]);
            }
        }
    }

    __syncthreads();   // all warps past the stage's last GEMM (X reads); stats visible

    // ---- X writeback in place ----
    #pragma unroll
    for (int g = 0; g < 2; g++) {
        const int cbase = g * 128 + n_grp * 32 + 2 * (lane & 3);
        #pragma unroll
        for (int mi = 0; mi < 2; mi++) {
            const int rA = m_grp * 32 + mi * 16 + rq;
            #pragma unroll
            for (int v = 0; v < 4; v++) {
                const int cc = cbase + v * 8;
                *(uint32_t*)(sm + SM_X + (uint32_t)rA * XPB + cc * 2)       = outr[g][mi][0][v];
                *(uint32_t*)(sm + SM_X + (uint32_t)(rA + 8) * XPB + cc * 2) = outr[g][mi][1][v];
            }
        }
    }
    // next boundary's sync orders these writes before reads
}

// ---------------- main fused kernel ----------------
__global__ void __launch_bounds__(NT, 2)
dec_main(const float* __restrict__ memory, const int* __restrict__ fidx,
         const float* __restrict__ bf, float* __restrict__ out)
{
    extern __shared__ __align__(16) uint8_t sm[];
    const int tid   = threadIdx.x;
    const int wid   = tid >> 5;
    const int lane  = tid & 31;
    const int m_grp = wid & 1;       // 0..1 (32-row block)
    const int n_grp = wid >> 1;      // 0..3 (32-col block within 128-col chunk)
    const int gr0   = blockIdx.x * TILE_M;
    const uint32_t smb = smem_u32_of(sm);

    // gather via cp.async from fp16 emb table
    #pragma unroll
    for (int i = tid; i < TILE_M * 32; i += NT) {      // 64 rows x 32 x 16B
        int row = i >> 5, c = i & 31;
        int e = __ldg(fidx + gr0 + row);
        CP_ASYNC16(smb + SM_X + (uint32_t)row * XPB + (c << 4),
                   (const uint8_t*)(g_embh + (size_t)e * DM) + (c << 4));
    }
    CP_COMMIT();
    issue_half(smb, tid, 0);

    stage_run<0>(sm, smb, tid, lane, m_grp, n_grp, gr0, memory, bf);
    stage_run<1>(sm, smb, tid, lane, m_grp, n_grp, gr0, memory, bf);
    stage_run<2>(sm, smb, tid, lane, m_grp, n_grp, gr0, memory, bf);

    // ---- logits: 64x64, Wo in ring slots (2 K-halves), warp tile 32M x 16N ----
    float acc[2][2][4] = {};
    #pragma unroll
    for (int kh = 0; kh < 2; kh++) {
        CP_WAIT0();
        __syncthreads();
        if (kh == 0) issue_half(smb, tid, 13);
        const uint32_t a_addr = smb + SM_X + (uint32_t)(m_grp * 32 + (lane & 15)) * XPB
                              + ((lane >> 4) << 4) + kh * 256;
        const uint32_t b_addr = smb + SM_W + (uint32_t)kh * SLOTSZ
                              + (uint32_t)(lane & 15) * WPB + ((lane >> 4) << 4) + n_grp * 32;
        #pragma unroll
        for (int k0 = 0; k0 < 128; k0 += 16) {
            uint32_t A0[4], A1[4], B0[4];
            ldsm_x4(A0, a_addr + k0 * 2);
            ldsm_x4(A1, a_addr + 16 * XPB + k0 * 2);
            ldsm_x4_t(B0, b_addr + (uint32_t)k0 * WPB);
            mma16816(acc[0][0], A0, B0); mma16816(acc[0][1], A0, B0 + 2);
            mma16816(acc[1][0], A1, B0); mma16816(acc[1][1], A1, B0 + 2);
        }
    }
    __syncthreads();   // all warps done reading Wo slots before logits overwrite SM_W

    #pragma unroll
    for (int mi = 0; mi < 2; mi++) {
        const int rlo = m_grp * 32 + mi * 16 + (lane >> 2);
        #pragma unroll
        for (int v = 0; v < 2; v++) {
            const int cc = n_grp * 16 + v * 8 + 2 * (lane & 3);
            *(float2*)(sm + SM_LG + (uint32_t)rlo * PPB + cc * 4)       = make_float2(acc[mi][v][0], acc[mi][v][1]);
            *(float2*)(sm + SM_LG + (uint32_t)(rlo + 8) * PPB + cc * 4) = make_float2(acc[mi][v][2], acc[mi][v][3]);
        }
    }
    __syncthreads();

    // ---- softmax: one thread per row ----
    if (tid < TILE_M) {
        uint8_t* rowp = sm + SM_LG + (uint32_t)tid * PPB;
        float4 v[16];
        float mx = -1e30f;
        #pragma unroll
        for (int i = 0; i < 16; i++) {
            v[i] = *(const float4*)(rowp + i * 16);
            mx = fmaxf(mx, fmaxf(fmaxf(v[i].x, v[i].y), fmaxf(v[i].z, v[i].w)));
        }
        float s = 0.f;
        #pragma unroll
        for (int i = 0; i < 16; i++) {
            v[i].x = __expf(v[i].x - mx); v[i].y = __expf(v[i].y - mx);
            v[i].z = __expf(v[i].z - mx); v[i].w = __expf(v[i].w - mx);
            s += (v[i].x + v[i].y) + (v[i].z + v[i].w);
        }
        const float inv = 1.0f / s;
        #pragma unroll
        for (int i = 0; i < 16; i++) {
            v[i].x *= inv; v[i].y *= inv; v[i].z *= inv; v[i].w *= inv;
            *(float4*)(rowp + i * 16) = v[i];
        }
    }
    __syncthreads();

    // ---- coalesced output store ----
    float* og = out + (size_t)gr0 * VOC;
    #pragma unroll
    for (int i = tid; i < TILE_M * VOC / 4; i += NT) {   // 1024 float4
        int row = i >> 4, c4 = i & 15;
        *(float4*)(og + row * VOC + c4 * 4) =
            *(const float4*)(sm + SM_LG + (uint32_t)row * PPB + c4 * 16);
    }
}

// ---------------- harness entry ----------------
extern "C" void kernel_launch(void* const* d_in, const int* in_sizes, int n_in,
                              void* d_out, int out_size)
{
    const float* memory   = (const float*)d_in[0];
    const int*   feat_idx = (const int*)  d_in[1];
    const float* emb      = (const float*)d_in[2];
    const float* Wf       = (const float*)d_in[3];
    const float* bf       = (const float*)d_in[4];
    const float* lg       = (const float*)d_in[5];
    const float* lb       = (const float*)d_in[6];
    const float* W1       = (const float*)d_in[7];
    const float* b1       = (const float*)d_in[8];
    const float* W2       = (const float*)d_in[9];
    const float* b2       = (const float*)d_in[10];
    const float* Wo       = (const float*)d_in[11];
    float* out = (float*)d_out;

    cudaFuncSetAttribute(dec_main, cudaFuncAttributeMaxDynamicSharedMemorySize, SMEM_BYTES);

    prep_weights<<<832, 256>>>(Wf, W1, W2, Wo, lg);
    prep_emb<<<4096, 256>>>(emb);
    prep_vecs<<<1, 256>>>(W1, b1, W2, b2, lg, lb);
    dec_main<<<GRID_M, NT, SMEM_BYTES>>>(memory, feat_idx, bf, out);
}

// round 9
// speedup vs baseline: 2.1442x; 1.2533x over previous
#include <cuda_runtime.h>
#include <cuda_fp16.h>
#include <math.h>
#include <stdint.h>

// ---------------- problem constants ----------------
#define NROWS   253952      // B*S*N = 16*512*31
#define DM      256
#define VOC     64
#define NN      31
#define VE      4096
#define TILE_M  64
#define GRID_M  (NROWS / TILE_M)   // 3968
#define NT      256

// ---------------- smem layout (bytes) ----------------
#define XPB     528           // activation row pitch (33*16 -> conflict-free ldsm)
#define WPB     272           // weight slot row pitch (17*16)
#define SLOTSZ  34816         // 128 k-rows * 272
#define PPB     272           // logits row pitch

#define SM_X    0             // 64*528 = 33792
#define SM_W    33792         // 2 slots -> 103424
#define SM_LG   SM_W          // logits reuse slot area
#define SM_ST   103424        // float2 [2 parity][4 slot][64 rows] = 4096
#define SMEM_BYTES 107520     // 2 CTAs/SM

// ---------------- prepped device globals ----------------
__device__ __align__(16) __half g_wf[65536];        // Wf fp16  [k][n]   (for prep_F)
__device__ __align__(16) __half g_w1g[65536];       // lg[k]*W1 [k][n]
__device__ __align__(16) __half g_w2g[65536];       // lg[k]*W2 [k][n]
__device__ __align__(16) __half g_wo[16384];        // W_out    [k][64]
__device__ __align__(16) __half g_embh[VE * 256];   // fp16 embedding (for prep_F)
__device__ __align__(16) __half g_F[VE * 256];      // F[e] = gelu(emb[e]@Wf + bf)
__device__ float g_d1[256], g_e1[256], g_d2[256], g_e2[256];

// ---------------- PTX helpers ----------------
__device__ __forceinline__ uint32_t smem_u32_of(const void* p) {
    uint32_t a;
    asm("{ .reg .u64 t; cvta.to.shared.u64 t, %1; cvt.u32.u64 %0, t; }" : "=r"(a) : "l"(p));
    return a;
}
__device__ __forceinline__ void ldsm_x4(uint32_t* r, uint32_t addr) {
    asm volatile("ldmatrix.sync.aligned.m8n8.x4.shared.b16 {%0,%1,%2,%3}, [%4];"
        : "=r"(r[0]), "=r"(r[1]), "=r"(r[2]), "=r"(r[3]) : "r"(addr));
}
__device__ __forceinline__ void ldsm_x4_t(uint32_t* r, uint32_t addr) {
    asm volatile("ldmatrix.sync.aligned.m8n8.x4.trans.shared.b16 {%0,%1,%2,%3}, [%4];"
        : "=r"(r[0]), "=r"(r[1]), "=r"(r[2]), "=r"(r[3]) : "r"(addr));
}
__device__ __forceinline__ void mma16816(float* d, const uint32_t* a, const uint32_t* b) {
    asm volatile("mma.sync.aligned.m16n8k16.row.col.f32.f16.f16.f32 "
        "{%0,%1,%2,%3}, {%4,%5,%6,%7}, {%8,%9}, {%0,%1,%2,%3};"
        : "+f"(d[0]), "+f"(d[1]), "+f"(d[2]), "+f"(d[3])
        : "r"(a[0]), "r"(a[1]), "r"(a[2]), "r"(a[3]), "r"(b[0]), "r"(b[1]));
}
#define CP_ASYNC16(dst, src) \
    asm volatile("cp.async.cg.shared.global [%0], [%1], 16;" :: "r"(dst), "l"(src) : "memory")
#define CP_COMMIT() asm volatile("cp.async.commit_group;" ::: "memory")
#define CP_WAIT0()  asm volatile("cp.async.wait_group 0;" ::: "memory")

// ---------------- math helpers ----------------
__device__ __forceinline__ float gelu_exact(float x) {
    return 0.5f * x * (1.0f + erff(x * 0.70710678118654752f));
}
__device__ __forceinline__ uint32_t pk(float a, float b) {
    __half2 h = __floats2half2_rn(a, b);
    return *reinterpret_cast<uint32_t*>(&h);
}
__device__ __forceinline__ float2 unpk(uint32_t u) {
    __half2 h = *reinterpret_cast<__half2*>(&u);
    return __half22float2(h);
}

// ---------------- prep kernels ----------------
__global__ void prep_weights(const float* __restrict__ Wf, const float* __restrict__ W1,
                             const float* __restrict__ W2, const float* __restrict__ Wo,
                             const float* __restrict__ lg) {
    int idx = blockIdx.x * blockDim.x + threadIdx.x;   // 832*256
    if (idx < 65536) {
        g_wf[idx] = __float2half_rn(Wf[idx]);
    } else if (idx < 131072) {
        int e = idx - 65536;
        g_w1g[e] = __float2half_rn(lg[e >> 8] * W1[e]);
    } else if (idx < 196608) {
        int e = idx - 131072;
        g_w2g[e] = __float2half_rn(lg[e >> 8] * W2[e]);
    } else {
        int e = idx - 196608;
        g_wo[e] = __float2half_rn(Wo[e]);
    }
}
__global__ void prep_emb(const float* __restrict__ emb) {
    int idx = blockIdx.x * blockDim.x + threadIdx.x;   // 4096*256
    g_embh[idx] = __float2half_rn(emb[idx]);
}
__global__ void prep_vecs(const float* __restrict__ W1, const float* __restrict__ b1,
                          const float* __restrict__ W2, const float* __restrict__ b2,
                          const float* __restrict__ lg, const float* __restrict__ lb) {
    int n = threadIdx.x;  // 256
    float d1 = 0.f, e1 = 0.f, d2 = 0.f, e2 = 0.f;
    for (int k = 0; k < 256; k++) {
        float g = lg[k], b = lb[k];
        float w1 = W1[k * 256 + n], w2 = W2[k * 256 + n];
        d1 += g * w1; e1 += b * w1;
        d2 += g * w2; e2 += b * w2;
    }
    g_d1[n] = d1; g_e1[n] = e1 + b1[n];
    g_d2[n] = d2; g_e2[n] = e2 + b2[n];
}

// F[e] = gelu(emb[e] @ Wf + bf), fp16 mma + fp32 epilogue. 64 CTAs x 64 rows.
#define FP_SMEM (33792 + 36864)   // A tile (64 x XPB) + W chunk (256 x 144)
__global__ void __launch_bounds__(256, 1)
prep_F(const float* __restrict__ bf) {
    extern __shared__ __align__(16) uint8_t sm[];
    const int tid = threadIdx.x, wid = tid >> 5, lane = tid & 31;
    const int row0 = blockIdx.x * 64;
    const uint32_t smb = smem_u32_of(sm);
    const uint32_t smA = smb, smW = smb + 33792;

    // load A: 64 emb rows fp16
    #pragma unroll
    for (int i = tid; i < 64 * 32; i += 256) {
        int row = i >> 5, c = i & 31;
        CP_ASYNC16(smA + (uint32_t)row * XPB + (c << 4),
                   (const uint8_t*)(g_embh + (size_t)(row0 + row) * 256) + (c << 4));
    }
    CP_COMMIT();

    const int m_grp = wid >> 1, n_grp = wid & 1;
    for (int j0 = 0; j0 < 256; j0 += 64) {
        __syncthreads();   // prior chunk fully consumed
        #pragma unroll
        for (int i = tid; i < 2048; i += 256) {   // 256 k-rows x 8 x 16B
            int k = i >> 3, c = i & 7;
            CP_ASYNC16(smW + k * 144 + (c << 4),
                       (const uint8_t*)(g_wf + (size_t)k * 256 + j0) + (c << 4));
        }
        CP_COMMIT();
        CP_WAIT0();
        __syncthreads();

        const uint32_t a_addr = smA + (uint32_t)(m_grp * 16 + (lane & 15)) * XPB + ((lane >> 4) << 4);
        const uint32_t b_addr = smW + (uint32_t)(lane & 15) * 144 + ((lane >> 4) << 4) + n_grp * 64;
        float acc[4][4] = {};
        #pragma unroll
        for (int k0 = 0; k0 < 256; k0 += 16) {
            uint32_t A[4], B0[4], B1[4];
            ldsm_x4(A, a_addr + k0 * 2);
            ldsm_x4_t(B0, b_addr + (uint32_t)k0 * 144);
            ldsm_x4_t(B1, b_addr + (uint32_t)k0 * 144 + 32);
            mma16816(acc[0], A, B0); mma16816(acc[1], A, B0 + 2);
            mma16816(acc[2], A, B1); mma16816(acc[3], A, B1 + 2);
        }
        const int rlo = m_grp * 16 + (lane >> 2), rhi = rlo + 8;
        #pragma unroll
        for (int v = 0; v < 4; v++) {
            const int col = j0 + n_grp * 32 + v * 8 + 2 * (lane & 3);
            float b0 = __ldg(bf + col), b1v = __ldg(bf + col + 1);
            *(uint32_t*)(g_F + (size_t)(row0 + rlo) * 256 + col) =
                pk(gelu_exact(acc[v][0] + b0), gelu_exact(acc[v][1] + b1v));
            *(uint32_t*)(g_F + (size_t)(row0 + rhi) * 256 + col) =
                pk(gelu_exact(acc[v][2] + b0), gelu_exact(acc[v][3] + b1v));
        }
    }
}

// ---------------- half-chunk issue (main kernel ring) ----------------
// h 0..3: W1g; h 4..7: W2g  (cols ((h>>1)&1)*128; K-half h&1)
// h 8,9:  Wo K-halves (64 cols)
__device__ __forceinline__ void issue_half(uint32_t smb, int tid, int h) {
    if (h > 9) return;
    uint32_t dst = smb + SM_W + (uint32_t)(h & 1) * SLOTSZ;
    if (h < 8) {
        const __half* W = (h < 4) ? g_w1g : g_w2g;
        const __half* src = W + (size_t)((h & 1) * 128) * 256 + ((h >> 1) & 1) * 128;
        #pragma unroll
        for (int i = tid; i < 2048; i += NT) {          // 128 k-rows x 16 x 16B
            int k = i >> 4, ch = i & 15;
            CP_ASYNC16(dst + k * WPB + (ch << 4),
                       (const uint8_t*)(src + (size_t)k * 256) + (ch << 4));
        }
    } else {
        const __half* src = g_wo + (size_t)((h & 1) * 128) * 64;
        #pragma unroll
        for (int i = tid; i < 1024; i += NT) {          // 128 k-rows x 8 x 16B
            int k = i >> 3, ch = i & 7;
            CP_ASYNC16(dst + k * WPB + (ch << 4),
                       (const uint8_t*)(src + (size_t)k * 64) + (ch << 4));
        }
    }
    CP_COMMIT();
}

// ---------------- one stage: 2 chunks x 128 cols, K in 2 ring halves ----------------
// S=1: W1g (reads stats parity 0, writes parity 1); S=2: W2g (reads parity 1)
template<int S>
__device__ __forceinline__ void stage_run(
    uint8_t* sm, uint32_t smb, int tid, int lane, int m_grp, int n_grp)
{
    const int rq = lane >> 2;
    const float* sD = (S == 1) ? g_d1 : g_d2;
    const float* sE = (S == 1) ? g_e1 : g_e2;
    const int hbase = 4 * (S - 1);

    // NOTE: caller must guarantee a __syncthreads() between the stats writes
    // (gather or previous stage) and entry here — these reads are cross-warp.
    float rs[4], mrs[4];
    #pragma unroll
    for (int q = 0; q < 4; q++) {
        int r = m_grp * 32 + (q >> 1) * 16 + (q & 1) * 8 + rq;
        const float2* stRd = (const float2*)(sm + SM_ST) + (uint32_t)((S - 1) & 1) * 256;
        float2 p0 = stRd[r], p1 = stRd[64 + r], p2 = stRd[128 + r], p3 = stRd[192 + r];
        float a1 = (p0.x + p1.x) + (p2.x + p3.x);
        float a2 = (p0.y + p1.y) + (p2.y + p3.y);
        float mu = a1 * (1.0f / 256.0f);
        rs[q]  = rsqrtf(a2 * (1.0f / 256.0f) - mu * mu + 1e-5f);
        mrs[q] = mu * rs[q];
    }

    uint32_t outr[2][2][2][4];
    float s1[4] = {0.f, 0.f, 0.f, 0.f}, s2[4] = {0.f, 0.f, 0.f, 0.f};

    #pragma unroll
    for (int g = 0; g < 2; g++) {
        float acc[2][4][4] = {};
        #pragma unroll
        for (int kh = 0; kh < 2; kh++) {
            const int h = hbase + 2 * g + kh;
            CP_WAIT0();
            __syncthreads();
            issue_half(smb, tid, h + 1);

            const uint32_t a_addr = smb + SM_X + (uint32_t)(m_grp * 32 + (lane & 15)) * XPB
                                  + ((lane >> 4) << 4) + kh * 256;
            const uint32_t b_addr = smb + SM_W + (uint32_t)(h & 1) * SLOTSZ
                                  + (uint32_t)(lane & 15) * WPB + ((lane >> 4) << 4) + n_grp * 64;
            #pragma unroll
            for (int k0 = 0; k0 < 128; k0 += 16) {
                uint32_t A0[4], A1[4], B0[4], B1[4];
                ldsm_x4(A0, a_addr + k0 * 2);
                ldsm_x4(A1, a_addr + 16 * XPB + k0 * 2);
                ldsm_x4_t(B0, b_addr + (uint32_t)k0 * WPB);
                ldsm_x4_t(B1, b_addr + (uint32_t)k0 * WPB + 32);
                mma16816(acc[0][0], A0, B0); mma16816(acc[0][1], A0, B0 + 2);
                mma16816(acc[0][2], A0, B1); mma16816(acc[0][3], A0, B1 + 2);
                mma16816(acc[1][0], A1, B0); mma16816(acc[1][1], A1, B0 + 2);
                mma16816(acc[1][2], A1, B1); mma16816(acc[1][3], A1, B1 + 2);
            }
        }

        const int cbase = g * 128 + n_grp * 32 + 2 * (lane & 3);
        #pragma unroll
        for (int mi = 0; mi < 2; mi++) {
            #pragma unroll
            for (int v = 0; v < 4; v++) {
                const int cc = cbase + v * 8;
                float2 dv = __ldg((const float2*)(sD + cc));
                float2 ev = __ldg((const float2*)(sE + cc));
                float x0 = gelu_exact(fmaf(rs[mi * 2], acc[mi][v][0], fmaf(-mrs[mi * 2], dv.x, ev.x)));
                float x1 = gelu_exact(fmaf(rs[mi * 2], acc[mi][v][1], fmaf(-mrs[mi * 2], dv.y, ev.y)));
                float x2 = gelu_exact(fmaf(rs[mi * 2 + 1], acc[mi][v][2], fmaf(-mrs[mi * 2 + 1], dv.x, ev.x)));
                float x3 = gelu_exact(fmaf(rs[mi * 2 + 1], acc[mi][v][3], fmaf(-mrs[mi * 2 + 1], dv.y, ev.y)));
                if (S == 1) {
                    s1[mi * 2]     += x0 + x1;  s2[mi * 2]     += x0 * x0 + x1 * x1;
                    s1[mi * 2 + 1] += x2 + x3;  s2[mi * 2 + 1] += x2 * x2 + x3 * x3;
                }
                outr[g][mi][0][v] = pk(x0, x1);
                outr[g][mi][1][v] = pk(x2, x3);
            }
        }
    }

    if (S == 1) {
        #pragma unroll
        for (int q = 0; q < 4; q++) {
            #pragma unroll
            for (int off = 1; off <= 2; off <<= 1) {
                s1[q] += __shfl_xor_sync(0xffffffffu, s1[q], off);
                s2[q] += __shfl_xor_sync(0xffffffffu, s2[q], off);
            }
        }
        if ((lane & 3) == 0) {
            float2* stWr = (float2*)(sm + SM_ST) + 256 + n_grp * 64;   // parity 1
            #pragma unroll
            for (int q = 0; q < 4; q++) {
                int r = m_grp * 32 + (q >> 1) * 16 + (q & 1) * 8 + rq;
                stWr[r] = make_float2(s1[q], s2[q]);
            }
        }
    }

    __syncthreads();   // all warps past last GEMM read of X; stats visible to next stage

    #pragma unroll
    for (int g = 0; g < 2; g++) {
        const int cbase = g * 128 + n_grp * 32 + 2 * (lane & 3);
        #pragma unroll
        for (int mi = 0; mi < 2; mi++) {
            const int rA = m_grp * 32 + mi * 16 + rq;
            #pragma unroll
            for (int v = 0; v < 4; v++) {
                const int cc = cbase + v * 8;
                *(uint32_t*)(sm + SM_X + (uint32_t)rA * XPB + cc * 2)       = outr[g][mi][0][v];
                *(uint32_t*)(sm + SM_X + (uint32_t)(rA + 8) * XPB + cc * 2) = outr[g][mi][1][v];
            }
        }
    }
}

// ---------------- main fused kernel ----------------
__global__ void __launch_bounds__(NT, 2)
dec_main(const float* __restrict__ memory, const int* __restrict__ fidx,
         float* __restrict__ out)
{
    extern __shared__ __align__(16) uint8_t sm[];
    const int tid   = threadIdx.x;
    const int wid   = tid >> 5;
    const int lane  = tid & 31;
    const int m_grp = wid & 1;       // 0..1 (32-row block)
    const int n_grp = wid >> 1;      // 0..3 (32-col block)
    const int gr0   = blockIdx.x * TILE_M;
    const uint32_t smb = smem_u32_of(sm);

    issue_half(smb, tid, 0);         // first W1g half in flight

    // ---- gather: X = F[feat_idx] + memory, fp16; stats -> parity 0 ----
    {
        const int r = tid >> 2, q = tid & 3;           // 64 rows x 4 quarters
        const int e = __ldg(fidx + gr0 + r);
        const uint4*  Fp = (const uint4*)(g_F + (size_t)e * DM + q * 64);
        const float4* Mp = (const float4*)(memory + (size_t)((gr0 + r) / NN) * DM + q * 64);
        float s1 = 0.f, s2 = 0.f;
        #pragma unroll
        for (int u = 0; u < 8; u++) {
            uint4 fv = __ldg(Fp + u);
            float4 ma = __ldg(Mp + 2 * u);
            float4 mb = __ldg(Mp + 2 * u + 1);
            float2 a0 = unpk(fv.x), a1 = unpk(fv.y), a2 = unpk(fv.z), a3 = unpk(fv.w);
            float x0 = a0.x + ma.x, x1 = a0.y + ma.y, x2 = a1.x + ma.z, x3 = a1.y + ma.w;
            float x4 = a2.x + mb.x, x5 = a2.y + mb.y, x6 = a3.x + mb.z, x7 = a3.y + mb.w;
            s1 += (x0 + x1) + (x2 + x3) + (x4 + x5) + (x6 + x7);
            s2 += x0*x0 + x1*x1 + x2*x2 + x3*x3 + x4*x4 + x5*x5 + x6*x6 + x7*x7;
            uint4 p;
            p.x = pk(x0, x1); p.y = pk(x2, x3); p.z = pk(x4, x5); p.w = pk(x6, x7);
            *(uint4*)(sm + SM_X + (uint32_t)r * XPB + q * 128 + (u << 4)) = p;
        }
        ((float2*)(sm + SM_ST))[q * 64 + r] = make_float2(s1, s2);   // parity 0, slot q
    }
    __syncthreads();   // *** stats (and X) visible before stage_run<1> reads them ***

    stage_run<1>(sm, smb, tid, lane, m_grp, n_grp);
    stage_run<2>(sm, smb, tid, lane, m_grp, n_grp);

    // ---- logits: 64x64, Wo halves h8,h9; warp tile 32M x 16N ----
    float acc[2][2][4] = {};
    #pragma unroll
    for (int kh = 0; kh < 2; kh++) {
        CP_WAIT0();
        __syncthreads();
        if (kh == 0) issue_half(smb, tid, 9);
        const uint32_t a_addr = smb + SM_X + (uint32_t)(m_grp * 32 + (lane & 15)) * XPB
                              + ((lane >> 4) << 4) + kh * 256;
        const uint32_t b_addr = smb + SM_W + (uint32_t)kh * SLOTSZ
                              + (uint32_t)(lane & 15) * WPB + ((lane >> 4) << 4) + n_grp * 32;
        #pragma unroll
        for (int k0 = 0; k0 < 128; k0 += 16) {
            uint32_t A0[4], A1[4], B0[4];
            ldsm_x4(A0, a_addr + k0 * 2);
            ldsm_x4(A1, a_addr + 16 * XPB + k0 * 2);
            ldsm_x4_t(B0, b_addr + (uint32_t)k0 * WPB);
            mma16816(acc[0][0], A0, B0); mma16816(acc[0][1], A0, B0 + 2);
            mma16816(acc[1][0], A1, B0); mma16816(acc[1][1], A1, B0 + 2);
        }
    }
    __syncthreads();   // all warps done reading Wo before logits overwrite SM_W

    #pragma unroll
    for (int mi = 0; mi < 2; mi++) {
        const int rlo = m_grp * 32 + mi * 16 + (lane >> 2);
        #pragma unroll
        for (int v = 0; v < 2; v++) {
            const int cc = n_grp * 16 + v * 8 + 2 * (lane & 3);
            *(float2*)(sm + SM_LG + (uint32_t)rlo * PPB + cc * 4)       = make_float2(acc[mi][v][0], acc[mi][v][1]);
            *(float2*)(sm + SM_LG + (uint32_t)(rlo + 8) * PPB + cc * 4) = make_float2(acc[mi][v][2], acc[mi][v][3]);
        }
    }
    __syncthreads();

    // ---- softmax: one thread per row ----
    if (tid < TILE_M) {
        uint8_t* rowp = sm + SM_LG + (uint32_t)tid * PPB;
        float4 v[16];
        float mx = -1e30f;
        #pragma unroll
        for (int i = 0; i < 16; i++) {
            v[i] = *(const float4*)(rowp + i * 16);
            mx = fmaxf(mx, fmaxf(fmaxf(v[i].x, v[i].y), fmaxf(v[i].z, v[i].w)));
        }
        float s = 0.f;
        #pragma unroll
        for (int i = 0; i < 16; i++) {
            v[i].x = __expf(v[i].x - mx); v[i].y = __expf(v[i].y - mx);
            v[i].z = __expf(v[i].z - mx); v[i].w = __expf(v[i].w - mx);
            s += (v[i].x + v[i].y) + (v[i].z + v[i].w);
        }
        const float inv = 1.0f / s;
        #pragma unroll
        for (int i = 0; i < 16; i++) {
            v[i].x *= inv; v[i].y *= inv; v[i].z *= inv; v[i].w *= inv;
            *(float4*)(rowp + i * 16) = v[i];
        }
    }
    __syncthreads();

    // ---- coalesced output store ----
    float* og = out + (size_t)gr0 * VOC;
    #pragma unroll
    for (int i = tid; i < TILE_M * VOC / 4; i += NT) {   // 1024 float4
        int row = i >> 4, c4 = i & 15;
        *(float4*)(og + row * VOC + c4 * 4) =
            *(const float4*)(sm + SM_LG + (uint32_t)row * PPB + c4 * 16);
    }
}

// ---------------- harness entry ----------------
extern "C" void kernel_launch(void* const* d_in, const int* in_sizes, int n_in,
                              void* d_out, int out_size)
{
    const float* memory   = (const float*)d_in[0];
    const int*   feat_idx = (const int*)  d_in[1];
    const float* emb      = (const float*)d_in[2];
    const float* Wf       = (const float*)d_in[3];
    const float* bf       = (const float*)d_in[4];
    const float* lg       = (const float*)d_in[5];
    const float* lb       = (const float*)d_in[6];
    const float* W1       = (const float*)d_in[7];
    const float* b1       = (const float*)d_in[8];
    const float* W2       = (const float*)d_in[9];
    const float* b2       = (const float*)d_in[10];
    const float* Wo       = (const float*)d_in[11];
    float* out = (float*)d_out;

    cudaFuncSetAttribute(dec_main, cudaFuncAttributeMaxDynamicSharedMemorySize, SMEM_BYTES);
    cudaFuncSetAttribute(prep_F,  cudaFuncAttributeMaxDynamicSharedMemorySize, FP_SMEM);

    prep_weights<<<832, 256>>>(Wf, W1, W2, Wo, lg);
    prep_emb<<<4096, 256>>>(emb);
    prep_vecs<<<1, 256>>>(W1, b1, W2, b2, lg, lb);
    prep_F<<<VE / 64, 256, FP_SMEM>>>(bf);
    dec_main<<<GRID_M, NT, SMEM_BYTES>>>(memory, feat_idx, out);
}